// round 11
// baseline (speedup 1.0000x reference)
#include <cuda_runtime.h>
#include <cuda_fp16.h>
#include <stdint.h>
#include <math.h>

// ---------------- problem constants ----------------
#define BATCH 32
#define NPROP 256
#define NCLS  19
#define NPTS  4096
#define NBQ   64
#define NCK   64
#define CDIM  256
#define QHD   768
#define VQ    8
#define NOUT  (VQ*QHD)                 // 6144
#define MROWS (BATCH*NBQ)              // 2048
#define FEAT_TOTAL ((size_t)BATCH*(NBQ+NCK)*VQ*QHD)
#define BOX_HALF   (NBQ*VQ*QHD)        // 393216

// pure fp16 K extents
#define K_BOX1  CDIM          // 256
#define K_CLK1  (2*CDIM)      // 512
#define K_G2    QHD           // 768

// ---------------- scratch ----------------
__device__ float g_mnp[BATCH*NPROP*3];
__device__ float g_mxp[BATCH*NPROP*3];
__device__ float g_volp[BATCH*NPROP];
__device__ float g_maskp[BATCH*NPROP];
__device__ float g_mnq[BATCH*NBQ*3];
__device__ float g_mxq[BATCH*NBQ*3];
__device__ float g_volq[BATCH*NBQ];
__device__ int   g_nn[MROWS];

__device__ __align__(128) __half g_Xbox  [(size_t)MROWS*K_BOX1];
__device__ __align__(128) __half g_Xclick[(size_t)MROWS*K_CLK1];
__device__ __align__(128) __half g_Hbox  [(size_t)MROWS*K_G2];
__device__ __align__(128) __half g_Hclick[(size_t)MROWS*K_G2];
__device__ __align__(128) __half g_Wb1[(size_t)QHD*CDIM];
__device__ __align__(128) __half g_Wc1[(size_t)QHD*2*CDIM];
__device__ __align__(128) __half g_Wb2[(size_t)NOUT*QHD];
__device__ __align__(128) __half g_Wc2[(size_t)NOUT*QHD];

// ---------------- helpers ----------------
static __device__ __forceinline__ uint32_t smem_u32(const void* p) {
    uint32_t a;
    asm("{ .reg .u64 t; cvta.to.shared.u64 t, %1; cvt.u32.u64 %0, t; }" : "=r"(a) : "l"(p));
    return a;
}
#define CPA16(s, g) asm volatile("cp.async.cg.shared.global [%0], [%1], 16;\n" :: "r"(s), "l"(g))
#define CPA_COMMIT() asm volatile("cp.async.commit_group;\n" ::: "memory")

#define LDMX4(r, a) \
    asm volatile("ldmatrix.sync.aligned.m8n8.x4.shared.b16 {%0,%1,%2,%3}, [%4];" \
        : "=r"((r)[0]), "=r"((r)[1]), "=r"((r)[2]), "=r"((r)[3]) : "r"(a))

#define MMA16816(d, a, b0_, b1_) \
    asm volatile("mma.sync.aligned.m16n8k16.row.col.f32.f16.f16.f32 " \
        "{%0,%1,%2,%3}, {%4,%5,%6,%7}, {%8,%9}, {%0,%1,%2,%3};" \
        : "+f"((d)[0]), "+f"((d)[1]), "+f"((d)[2]), "+f"((d)[3]) \
        : "r"((a)[0]), "r"((a)[1]), "r"((a)[2]), "r"((a)[3]), "r"(b0_), "r"(b1_))

// ---------------- prep kernels ----------------
__global__ void prep_props_kernel(const float* __restrict__ logits,
                                  const float* __restrict__ corners) {
    int i = blockIdx.x * blockDim.x + threadIdx.x;
    if (i >= BATCH*NPROP) return;
    const float* lg = logits + (size_t)i*NCLS;
    int am = 0; float best = lg[0];
    #pragma unroll
    for (int c = 1; c < NCLS; c++) { float v = lg[c]; if (v > best) { best = v; am = c; } }
    g_maskp[i] = (am != NCLS-1) ? 1.0f : 0.0f;
    const float* cr = corners + (size_t)i*24;
    float mn[3] = {cr[0], cr[1], cr[2]};
    float mx[3] = {cr[0], cr[1], cr[2]};
    #pragma unroll
    for (int k = 1; k < 8; k++)
        #pragma unroll
        for (int d = 0; d < 3; d++) {
            float v = cr[k*3+d];
            mn[d] = fminf(mn[d], v); mx[d] = fmaxf(mx[d], v);
        }
    float vol = 1.0f;
    #pragma unroll
    for (int d = 0; d < 3; d++) {
        g_mnp[i*3+d] = mn[d]; g_mxp[i*3+d] = mx[d];
        vol *= (mx[d] - mn[d]);
    }
    g_volp[i] = vol;
}

__global__ void prep_queries_kernel(const float* __restrict__ box_query) {
    int i = blockIdx.x * blockDim.x + threadIdx.x;
    if (i >= BATCH*NBQ) return;
    const float* cr = box_query + (size_t)i*24;
    float mn[3] = {cr[0], cr[1], cr[2]};
    float mx[3] = {cr[0], cr[1], cr[2]};
    #pragma unroll
    for (int k = 1; k < 8; k++)
        #pragma unroll
        for (int d = 0; d < 3; d++) {
            float v = cr[k*3+d];
            mn[d] = fminf(mn[d], v); mx[d] = fmaxf(mx[d], v);
        }
    float vol = 1.0f;
    #pragma unroll
    for (int d = 0; d < 3; d++) {
        g_mnq[i*3+d] = mn[d]; g_mxq[i*3+d] = mx[d];
        vol *= (mx[d] - mn[d]);
    }
    g_volq[i] = vol;
}

__global__ __launch_bounds__(256) void box_match_kernel(const float* __restrict__ prop_features) {
    int m = blockIdx.x;
    int b = m >> 6;
    int tid = threadIdx.x;
    float mnq0 = g_mnq[m*3+0], mnq1 = g_mnq[m*3+1], mnq2 = g_mnq[m*3+2];
    float mxq0 = g_mxq[m*3+0], mxq1 = g_mxq[m*3+1], mxq2 = g_mxq[m*3+2];
    float volq = g_volq[m];
    int pi = b*NPROP + tid;
    float i0 = fmaxf(fminf(mxq0, g_mxp[pi*3+0]) - fmaxf(mnq0, g_mnp[pi*3+0]), 0.0f);
    float i1 = fmaxf(fminf(mxq1, g_mxp[pi*3+1]) - fmaxf(mnq1, g_mnp[pi*3+1]), 0.0f);
    float i2 = fmaxf(fminf(mxq2, g_mxp[pi*3+2]) - fmaxf(mnq2, g_mnp[pi*3+2]), 0.0f);
    float inter = i0*i1*i2;
    float iou = inter / (volq + g_volp[pi] - inter + 1e-8f);
    iou *= g_maskp[pi];

    __shared__ float sv[256];
    __shared__ int   si[256];
    sv[tid] = iou; si[tid] = tid;
    __syncthreads();
    #pragma unroll
    for (int off = 128; off > 0; off >>= 1) {
        if (tid < off) {
            float v2 = sv[tid+off]; int j2 = si[tid+off];
            if (v2 > sv[tid] || (v2 == sv[tid] && j2 < si[tid])) { sv[tid] = v2; si[tid] = j2; }
        }
        __syncthreads();
    }
    int idx = si[0];
    float v = prop_features[((size_t)b*NPROP + idx)*CDIM + tid];
    g_Xbox[(size_t)m*K_BOX1 + tid] = __float2half(v);
}

// ---------------- click NN: one block per batch, smem-cached xyz ----------------
__global__ __launch_bounds__(256) void click_nn_kernel(
    const float* __restrict__ click_query, const float* __restrict__ enc_xyz) {
    __shared__ float sx[2048], sy[2048], sz[2048];
    int b = blockIdx.x;
    int tid = threadIdx.x, w = tid >> 5, lane = tid & 31;

    // each warp owns 8 clicks
    float qx[8], qy[8], qz[8];
    #pragma unroll
    for (int j = 0; j < 8; j++) {
        const float* q = click_query + ((size_t)b*NCK + w*8 + j)*3;
        qx[j] = q[0]; qy[j] = q[1]; qz[j] = q[2];
    }
    float bd[8]; int bi[8];
    #pragma unroll
    for (int j = 0; j < 8; j++) { bd[j] = 3.4e38f; bi[j] = 0; }

    for (int t = 0; t < 2; t++) {
        __syncthreads();
        const float* src = enc_xyz + ((size_t)b*NPTS + t*2048)*3;
        #pragma unroll
        for (int i = 0; i < 24; i++) {
            int f = tid + 256*i;
            float v = src[f];
            int p = f/3, d = f - p*3;
            if (d == 0) sx[p] = v; else if (d == 1) sy[p] = v; else sz[p] = v;
        }
        __syncthreads();
        for (int i = 0; i < 64; i++) {
            int p = lane + 32*i;
            float x = sx[p], y = sy[p], z = sz[p];
            int gidx = t*2048 + p;
            #pragma unroll
            for (int j = 0; j < 8; j++) {
                float dx = qx[j]-x, dy = qy[j]-y, dz = qz[j]-z;
                float d2 = dx*dx + dy*dy + dz*dz;
                if (d2 < bd[j]) { bd[j] = d2; bi[j] = gidx; }
            }
        }
    }
    // warp-level reduction, first-min tie break (smaller index wins on equal d2)
    #pragma unroll
    for (int j = 0; j < 8; j++) {
        float d = bd[j]; int idx = bi[j];
        #pragma unroll
        for (int off = 16; off > 0; off >>= 1) {
            float od = __shfl_down_sync(0xffffffffu, d, off);
            int   oi = __shfl_down_sync(0xffffffffu, idx, off);
            if (od < d || (od == d && oi < idx)) { d = od; idx = oi; }
        }
        if (lane == 0) g_nn[b*NCK + w*8 + j] = idx;
    }
}

// ---------------- click gather + fourier ----------------
__global__ __launch_bounds__(256) void click_gather_kernel(
    const float* __restrict__ click_query, const float* __restrict__ enc_features,
    const float* __restrict__ pc_min, const float* __restrict__ pc_max,
    const float* __restrict__ gauss_B) {
    int m = blockIdx.x;
    int b = m >> 6;
    int tid = threadIdx.x;
    int nn = g_nn[m];
    size_t rb = (size_t)m*K_CLK1;
    g_Xclick[rb + tid] = __float2half(enc_features[((size_t)b*NPTS + nn)*CDIM + tid]);
    if (tid < 128) {
        float qx = click_query[m*3+0], qy = click_query[m*3+1], qz = click_query[m*3+2];
        float x0 = (qx - pc_min[b*3+0]) / (pc_max[b*3+0] - pc_min[b*3+0]);
        float y0 = (qy - pc_min[b*3+1]) / (pc_max[b*3+1] - pc_min[b*3+1]);
        float z0 = (qz - pc_min[b*3+2]) / (pc_max[b*3+2] - pc_min[b*3+2]);
        const float twopi = 6.283185307179586f;
        float proj = (x0*twopi)*gauss_B[tid] + (y0*twopi)*gauss_B[128+tid] + (z0*twopi)*gauss_B[256+tid];
        g_Xclick[rb + CDIM + tid]       = __float2half(sinf(proj));
        g_Xclick[rb + CDIM + 128 + tid] = __float2half(cosf(proj));
    }
}

// ---------------- weight conversion: W[K,N] fp32 -> Wh[N,K] fp16 ----------------
__global__ __launch_bounds__(256) void conv_weight_kernel(
    const float* __restrict__ W, __half* __restrict__ B2, int K, int N) {
    __shared__ float t[32][33];
    int n0 = blockIdx.x * 32, k0 = blockIdx.y * 32;
    int tx = threadIdx.x, ty = threadIdx.y;   // block (32,8)
    #pragma unroll
    for (int j = 0; j < 4; j++) {
        int k = k0 + ty + j*8;
        t[ty + j*8][tx] = W[(size_t)k*N + n0 + tx];
    }
    __syncthreads();
    #pragma unroll
    for (int j = 0; j < 4; j++) {
        int n = n0 + ty + j*8;
        int k = k0 + tx;
        B2[(size_t)n*K + k] = __float2half(t[tx][ty + j*8]);
    }
}

// ---------------- HMMA fp16 GEMM (templated on BN) ----------------
// D[M,N] = A[M,K] x B[N,K]^T; CTA tile 128xBNT, warp tile 64x(BNT/4),
// 2x4 warps, BK=64, 3-stage cp.async pipeline.
// mode 0: relu(d+bias) -> fp16 into outB [M,QHD]
// mode 1: d+bias -> outF + m*6144 + (m>>6)*BOX_HALF
// mode 2: same + BOX_HALF
#define BM 128
#define OFF_STAGE 1024

template<int BNT>
static __device__ __forceinline__ void load_chunk(
    const __half* A2, const __half* B2, int K,
    int bm, int bn, int c, uint32_t sbase, int stage)
{
    constexpr int ASTG = 16384;
    constexpr int STG = ASTG + BNT*128;
    int t = threadIdx.x;
    uint32_t stA = sbase + OFF_STAGE + stage*STG;
    uint32_t stB = stA + ASTG;
    // A: 128 rows x 128B = 1024 16B-units; 4 per thread
    #pragma unroll
    for (int i = 0; i < 4; i++) {
        int u = t + 256*i;
        int r = u >> 3, c16 = u & 7;
        uint32_t off = (uint32_t)r*128 + (uint32_t)((c16 ^ (r & 7)) << 4);
        CPA16(stA + off, (const char*)(A2 + (size_t)(bm + r)*K + c*64) + (c16 << 4));
    }
    // B: BNT rows x 128B = BNT*8 16B-units; BNT/32 per thread
    #pragma unroll
    for (int i = 0; i < BNT/32; i++) {
        int u = t + 256*i;
        int r = u >> 3, c16 = u & 7;
        uint32_t off = (uint32_t)r*128 + (uint32_t)((c16 ^ (r & 7)) << 4);
        CPA16(stB + off, (const char*)(B2 + (size_t)(bn + r)*K + c*64) + (c16 << 4));
    }
}

template<int BNT>
__global__ __launch_bounds__(256) void gemm_hmma_kernel(
    const __half* A0, const __half* B0, const float* bias0,
    const __half* A1, const __half* B1, const float* bias1,
    int k0_, int k1_, int mode0_, int mode1_,
    float* outF, __half* outB0, __half* outB1)
{
    constexpr int NJ = BNT/32;       // n-frags of 8 per warp
    constexpr int NT = NJ/2;         // ldmatrix groups of 16 rows
    constexpr int ASTG = 16384;
    constexpr int STG = ASTG + BNT*128;
    extern __shared__ char smem[];
    const int z = blockIdx.z;
    const __half* A2 = z ? A1 : A0;
    const __half* B2 = z ? B1 : B0;
    const float* bias = z ? bias1 : bias0;
    __half* outB = z ? outB1 : outB0;
    const int K = z ? k1_ : k0_;
    const int mode = z ? mode1_ : mode0_;
    const int bm = blockIdx.y * BM, bn = blockIdx.x * BNT;
    const int tid = threadIdx.x, wid = tid >> 5, lane = tid & 31;
    const int warp_m = wid >> 2, warp_n = wid & 3;
    uint32_t sbase = smem_u32(smem);
    float* sBias = (float*)smem;
    if (tid < BNT) sBias[tid] = bias[bn + tid];

    float acc[4][NJ][4];
    #pragma unroll
    for (int mi = 0; mi < 4; mi++)
        #pragma unroll
        for (int nj = 0; nj < NJ; nj++)
            #pragma unroll
            for (int e = 0; e < 4; e++) acc[mi][nj][e] = 0.0f;

    const int nch = K >> 6;
    load_chunk<BNT>(A2, B2, K, bm, bn, 0, sbase, 0); CPA_COMMIT();
    load_chunk<BNT>(A2, B2, K, bm, bn, 1, sbase, 1); CPA_COMMIT();
    load_chunk<BNT>(A2, B2, K, bm, bn, 2, sbase, 2); CPA_COMMIT();

    const int lane15 = lane & 15, s7 = lane & 7, hic = lane >> 4;

    for (int c = 0; c < nch; c++) {
        int s = c - (c/3)*3;
        if (c + 3 < nch) { asm volatile("cp.async.wait_group 2;\n" ::: "memory"); }
        else             { asm volatile("cp.async.wait_group 0;\n" ::: "memory"); }
        __syncthreads();

        uint32_t stA = sbase + OFF_STAGE + s*STG;
        uint32_t stB = stA + ASTG;
        uint32_t aBase[4], bBase[NT];
        #pragma unroll
        for (int mi = 0; mi < 4; mi++)
            aBase[mi] = stA + (uint32_t)(warp_m*64 + mi*16 + lane15) * 128;
        #pragma unroll
        for (int nt = 0; nt < NT; nt++)
            bBase[nt] = stB + (uint32_t)(warp_n*(BNT/4) + nt*16 + lane15) * 128;

        #pragma unroll
        for (int ks = 0; ks < 4; ks++) {
            uint32_t coff = (uint32_t)(((2*ks + hic) ^ s7) << 4);
            uint32_t afr[4][4], bfr[NT][4];
            #pragma unroll
            for (int mi = 0; mi < 4; mi++) LDMX4(afr[mi], aBase[mi] + coff);
            #pragma unroll
            for (int nt = 0; nt < NT; nt++) LDMX4(bfr[nt], bBase[nt] + coff);
            #pragma unroll
            for (int mi = 0; mi < 4; mi++)
                #pragma unroll
                for (int nj = 0; nj < NJ; nj++)
                    MMA16816(acc[mi][nj], afr[mi],
                             bfr[nj>>1][nj&1], bfr[nj>>1][2 + (nj&1)]);
        }
        __syncthreads();
        if (c + 3 < nch) {
            load_chunk<BNT>(A2, B2, K, bm, bn, c + 3, sbase, s);
            CPA_COMMIT();
        }
    }

    // ---- epilogue ----
    #pragma unroll
    for (int mi = 0; mi < 4; mi++) {
        int rr0 = warp_m*64 + mi*16 + (lane >> 2);
        #pragma unroll
        for (int h = 0; h < 2; h++) {
            int m = bm + rr0 + 8*h;
            size_t rowbase;
            if (mode == 0) rowbase = (size_t)m * K_G2;
            else {
                rowbase = (size_t)m * NOUT + (size_t)(m >> 6) * BOX_HALF;
                if (mode == 2) rowbase += BOX_HALF;
            }
            #pragma unroll
            for (int nj = 0; nj < NJ; nj++) {
                int cc = warp_n*(BNT/4) + nj*8 + 2*(lane & 3);
                float v0 = acc[mi][nj][2*h+0] + sBias[cc];
                float v1 = acc[mi][nj][2*h+1] + sBias[cc+1];
                if (mode == 0) {
                    v0 = fmaxf(v0, 0.0f); v1 = fmaxf(v1, 0.0f);
                    __half2 hp; hp.x = __float2half(v0); hp.y = __float2half(v1);
                    *(__half2*)&outB[rowbase + (size_t)(bn + cc)] = hp;
                } else {
                    float2 v; v.x = v0; v.y = v1;
                    *(float2*)&outF[rowbase + bn + cc] = v;
                }
            }
        }
    }
}

#define GEMM_SMEM_128 (OFF_STAGE + 3*(16384 + 128*128))   // 99328
#define GEMM_SMEM_256 (OFF_STAGE + 3*(16384 + 256*128))   // 148480

// ---------------- mask tail ----------------
__global__ void mask_fill_kernel(const float* __restrict__ box_qmask,
                                 const float* __restrict__ click_qmask,
                                 float* __restrict__ out) {
    int i = blockIdx.x * blockDim.x + threadIdx.x;
    if (i >= BATCH * (NBQ+NCK) * VQ) return;
    int b = i / ((NBQ+NCK)*VQ);
    int s = i % ((NBQ+NCK)*VQ);
    float v;
    if (s < NBQ*VQ) v = box_qmask[b*NBQ + (s >> 3)];
    else            v = click_qmask[b*NCK + ((s - NBQ*VQ) >> 3)];
    out[FEAT_TOTAL + i] = v;
}

// ---------------- launch ----------------
extern "C" void kernel_launch(void* const* d_in, const int* in_sizes, int n_in,
                              void* d_out, int out_size) {
    const float* sem_cls_logits = (const float*)d_in[0];
    const float* prop_features  = (const float*)d_in[1];
    const float* box_corners    = (const float*)d_in[2];
    const float* enc_xyz        = (const float*)d_in[3];
    const float* enc_features   = (const float*)d_in[4];
    const float* pc_min         = (const float*)d_in[5];
    const float* pc_max         = (const float*)d_in[6];
    const float* box_query      = (const float*)d_in[7];
    const float* box_qmask      = (const float*)d_in[8];
    const float* click_query    = (const float*)d_in[9];
    const float* click_qmask    = (const float*)d_in[10];
    const float* gauss_B        = (const float*)d_in[11];
    const float* box_w1         = (const float*)d_in[12];
    const float* box_b1         = (const float*)d_in[13];
    const float* box_w2         = (const float*)d_in[14];
    const float* box_b2         = (const float*)d_in[15];
    const float* click_w1       = (const float*)d_in[16];
    const float* click_b1       = (const float*)d_in[17];
    const float* click_w2       = (const float*)d_in[18];
    const float* click_b2       = (const float*)d_in[19];
    float* out = (float*)d_out;

    __half *Xb, *Xc, *Hb, *Hc, *Wb1, *Wc1, *Wb2, *Wc2;
    cudaGetSymbolAddress((void**)&Xb,  g_Xbox);
    cudaGetSymbolAddress((void**)&Xc,  g_Xclick);
    cudaGetSymbolAddress((void**)&Hb,  g_Hbox);
    cudaGetSymbolAddress((void**)&Hc,  g_Hclick);
    cudaGetSymbolAddress((void**)&Wb1, g_Wb1);
    cudaGetSymbolAddress((void**)&Wc1, g_Wc1);
    cudaGetSymbolAddress((void**)&Wb2, g_Wb2);
    cudaGetSymbolAddress((void**)&Wc2, g_Wc2);

    cudaFuncSetAttribute(gemm_hmma_kernel<128>,
                         cudaFuncAttributeMaxDynamicSharedMemorySize, GEMM_SMEM_128);
    cudaFuncSetAttribute(gemm_hmma_kernel<256>,
                         cudaFuncAttributeMaxDynamicSharedMemorySize, GEMM_SMEM_256);

    // prep
    prep_props_kernel<<<(BATCH*NPROP + 255)/256, 256>>>(sem_cls_logits, box_corners);
    prep_queries_kernel<<<(BATCH*NBQ + 255)/256, 256>>>(box_query);
    box_match_kernel<<<MROWS, 256>>>(prop_features);
    click_nn_kernel<<<BATCH, 256>>>(click_query, enc_xyz);
    click_gather_kernel<<<MROWS, 256>>>(click_query, enc_features,
                                        pc_min, pc_max, gauss_B);
    // weight conversion (W[K,N] fp32 -> Wh[N,K] fp16)
    {
        dim3 blk(32, 8);
        conv_weight_kernel<<<dim3(QHD/32, CDIM/32),     blk>>>(box_w1,   Wb1, CDIM,   QHD);
        conv_weight_kernel<<<dim3(QHD/32, 2*CDIM/32),   blk>>>(click_w1, Wc1, 2*CDIM, QHD);
        conv_weight_kernel<<<dim3(NOUT/32, QHD/32),     blk>>>(box_w2,   Wb2, QHD,    NOUT);
        conv_weight_kernel<<<dim3(NOUT/32, QHD/32),     blk>>>(click_w2, Wc2, QHD,    NOUT);
    }
    // GEMM1 (both branches): X @ W1 + b1, relu -> H (fp16); BN=128 -> 192 CTAs
    gemm_hmma_kernel<128><<<dim3(QHD/128, MROWS/BM, 2), 256, GEMM_SMEM_128>>>(
        Xb, Wb1, box_b1, Xc, Wc1, click_b1,
        K_BOX1, K_CLK1, 0, 0, nullptr, Hb, Hc);
    // GEMM2 (both branches): H @ W2 + b2 -> out (interleaved layout); BN=256
    gemm_hmma_kernel<256><<<dim3(NOUT/256, MROWS/BM, 2), 256, GEMM_SMEM_256>>>(
        Hb, Wb2, box_b2, Hc, Wc2, click_b2,
        K_G2, K_G2, 1, 2, out, nullptr, nullptr);

    mask_fill_kernel<<<(BATCH*(NBQ+NCK)*VQ + 255)/256, 256>>>(box_qmask, click_qmask, out);
}

// round 12
// speedup vs baseline: 1.5516x; 1.5516x over previous
#include <cuda_runtime.h>
#include <cuda_fp16.h>
#include <stdint.h>
#include <math.h>

// ---------------- problem constants ----------------
#define BATCH 32
#define NPROP 256
#define NCLS  19
#define NPTS  4096
#define NBQ   64
#define NCK   64
#define CDIM  256
#define QHD   768
#define VQ    8
#define NOUT  (VQ*QHD)                 // 6144
#define MROWS (BATCH*NBQ)              // 2048
#define FEAT_TOTAL ((size_t)BATCH*(NBQ+NCK)*VQ*QHD)
#define BOX_HALF   (NBQ*VQ*QHD)        // 393216

// pure fp16 K extents
#define K_BOX1  CDIM          // 256
#define K_CLK1  (2*CDIM)      // 512
#define K_G2    QHD           // 768

// ---------------- scratch ----------------
__device__ float g_mnp[BATCH*NPROP*3];
__device__ float g_mxp[BATCH*NPROP*3];
__device__ float g_volp[BATCH*NPROP];
__device__ float g_maskp[BATCH*NPROP];
__device__ float g_mnq[BATCH*NBQ*3];
__device__ float g_mxq[BATCH*NBQ*3];
__device__ float g_volq[BATCH*NBQ];

__device__ __align__(128) __half g_Xbox  [(size_t)MROWS*K_BOX1];
__device__ __align__(128) __half g_Xclick[(size_t)MROWS*K_CLK1];
__device__ __align__(128) __half g_Hbox  [(size_t)MROWS*K_G2];
__device__ __align__(128) __half g_Hclick[(size_t)MROWS*K_G2];
__device__ __align__(128) __half g_Wb1[(size_t)QHD*CDIM];
__device__ __align__(128) __half g_Wc1[(size_t)QHD*2*CDIM];
__device__ __align__(128) __half g_Wb2[(size_t)NOUT*QHD];
__device__ __align__(128) __half g_Wc2[(size_t)NOUT*QHD];

// ---------------- helpers ----------------
static __device__ __forceinline__ uint32_t smem_u32(const void* p) {
    uint32_t a;
    asm("{ .reg .u64 t; cvta.to.shared.u64 t, %1; cvt.u32.u64 %0, t; }" : "=r"(a) : "l"(p));
    return a;
}
#define CPA16(s, g) asm volatile("cp.async.cg.shared.global [%0], [%1], 16;\n" :: "r"(s), "l"(g))
#define CPA_COMMIT() asm volatile("cp.async.commit_group;\n" ::: "memory")

#define LDMX4(r, a) \
    asm volatile("ldmatrix.sync.aligned.m8n8.x4.shared.b16 {%0,%1,%2,%3}, [%4];" \
        : "=r"((r)[0]), "=r"((r)[1]), "=r"((r)[2]), "=r"((r)[3]) : "r"(a))

#define MMA16816(d, a, b0_, b1_) \
    asm volatile("mma.sync.aligned.m16n8k16.row.col.f32.f16.f16.f32 " \
        "{%0,%1,%2,%3}, {%4,%5,%6,%7}, {%8,%9}, {%0,%1,%2,%3};" \
        : "+f"((d)[0]), "+f"((d)[1]), "+f"((d)[2]), "+f"((d)[3]) \
        : "r"((a)[0]), "r"((a)[1]), "r"((a)[2]), "r"((a)[3]), "r"(b0_), "r"(b1_))

// ---------------- prep kernels ----------------
__global__ void prep_props_kernel(const float* __restrict__ logits,
                                  const float* __restrict__ corners) {
    int i = blockIdx.x * blockDim.x + threadIdx.x;
    if (i >= BATCH*NPROP) return;
    const float* lg = logits + (size_t)i*NCLS;
    int am = 0; float best = lg[0];
    #pragma unroll
    for (int c = 1; c < NCLS; c++) { float v = lg[c]; if (v > best) { best = v; am = c; } }
    g_maskp[i] = (am != NCLS-1) ? 1.0f : 0.0f;
    const float* cr = corners + (size_t)i*24;
    float mn[3] = {cr[0], cr[1], cr[2]};
    float mx[3] = {cr[0], cr[1], cr[2]};
    #pragma unroll
    for (int k = 1; k < 8; k++)
        #pragma unroll
        for (int d = 0; d < 3; d++) {
            float v = cr[k*3+d];
            mn[d] = fminf(mn[d], v); mx[d] = fmaxf(mx[d], v);
        }
    float vol = 1.0f;
    #pragma unroll
    for (int d = 0; d < 3; d++) {
        g_mnp[i*3+d] = mn[d]; g_mxp[i*3+d] = mx[d];
        vol *= (mx[d] - mn[d]);
    }
    g_volp[i] = vol;
}

__global__ void prep_queries_kernel(const float* __restrict__ box_query) {
    int i = blockIdx.x * blockDim.x + threadIdx.x;
    if (i >= BATCH*NBQ) return;
    const float* cr = box_query + (size_t)i*24;
    float mn[3] = {cr[0], cr[1], cr[2]};
    float mx[3] = {cr[0], cr[1], cr[2]};
    #pragma unroll
    for (int k = 1; k < 8; k++)
        #pragma unroll
        for (int d = 0; d < 3; d++) {
            float v = cr[k*3+d];
            mn[d] = fminf(mn[d], v); mx[d] = fmaxf(mx[d], v);
        }
    float vol = 1.0f;
    #pragma unroll
    for (int d = 0; d < 3; d++) {
        g_mnq[i*3+d] = mn[d]; g_mxq[i*3+d] = mx[d];
        vol *= (mx[d] - mn[d]);
    }
    g_volq[i] = vol;
}

__global__ __launch_bounds__(256) void box_match_kernel(const float* __restrict__ prop_features) {
    int m = blockIdx.x;
    int b = m >> 6;
    int tid = threadIdx.x;
    float mnq0 = g_mnq[m*3+0], mnq1 = g_mnq[m*3+1], mnq2 = g_mnq[m*3+2];
    float mxq0 = g_mxq[m*3+0], mxq1 = g_mxq[m*3+1], mxq2 = g_mxq[m*3+2];
    float volq = g_volq[m];
    int pi = b*NPROP + tid;
    float i0 = fmaxf(fminf(mxq0, g_mxp[pi*3+0]) - fmaxf(mnq0, g_mnp[pi*3+0]), 0.0f);
    float i1 = fmaxf(fminf(mxq1, g_mxp[pi*3+1]) - fmaxf(mnq1, g_mnp[pi*3+1]), 0.0f);
    float i2 = fmaxf(fminf(mxq2, g_mxp[pi*3+2]) - fmaxf(mnq2, g_mnp[pi*3+2]), 0.0f);
    float inter = i0*i1*i2;
    float iou = inter / (volq + g_volp[pi] - inter + 1e-8f);
    iou *= g_maskp[pi];

    __shared__ float sv[256];
    __shared__ int   si[256];
    sv[tid] = iou; si[tid] = tid;
    __syncthreads();
    #pragma unroll
    for (int off = 128; off > 0; off >>= 1) {
        if (tid < off) {
            float v2 = sv[tid+off]; int j2 = si[tid+off];
            if (v2 > sv[tid] || (v2 == sv[tid] && j2 < si[tid])) { sv[tid] = v2; si[tid] = j2; }
        }
        __syncthreads();
    }
    int idx = si[0];
    float v = prop_features[((size_t)b*NPROP + idx)*CDIM + tid];
    g_Xbox[(size_t)m*K_BOX1 + tid] = __float2half(v);
}

// ---------------- click prep: 8 blocks/batch, 1 warp/click, smem-tiled NN ----------------
#define NN_TILE 1024
__global__ __launch_bounds__(256) void click_prep_kernel(
    const float* __restrict__ click_query, const float* __restrict__ enc_xyz,
    const float* __restrict__ enc_features, const float* __restrict__ pc_min,
    const float* __restrict__ pc_max, const float* __restrict__ gauss_B) {
    __shared__ float sx[NN_TILE], sy[NN_TILE], sz[NN_TILE];
    int b = blockIdx.x >> 3;          // batch
    int g = blockIdx.x & 7;           // click octet within batch
    int tid = threadIdx.x, w = tid >> 5, lane = tid & 31;
    int ck = g*8 + w;                 // click index within batch (warp-owned)
    int m = b*NCK + ck;               // global click row

    float qx = click_query[m*3+0], qy = click_query[m*3+1], qz = click_query[m*3+2];
    float bd = 3.4e38f; int bi = 0;

    #pragma unroll 1
    for (int t = 0; t < NPTS/NN_TILE; t++) {
        __syncthreads();
        const float* src = enc_xyz + ((size_t)b*NPTS + t*NN_TILE)*3;
        // 3*NN_TILE floats, 256 threads, 12 each; coalesced read, scatter to SoA
        #pragma unroll
        for (int i = 0; i < 3*NN_TILE/256; i++) {
            int f = tid + 256*i;
            float v = src[f];
            int p = f/3, d = f - p*3;
            if (d == 0) sx[p] = v; else if (d == 1) sy[p] = v; else sz[p] = v;
        }
        __syncthreads();
        // each warp scans the tile for its click; ascending index keeps first-min
        #pragma unroll 4
        for (int i = 0; i < NN_TILE/32; i++) {
            int p = lane + 32*i;
            float dx = qx - sx[p], dy = qy - sy[p], dz = qz - sz[p];
            float d2 = dx*dx + dy*dy + dz*dz;
            if (d2 < bd) { bd = d2; bi = t*NN_TILE + p; }
        }
    }
    // warp reduction, first-min tie break (smaller index wins on equal d2)
    #pragma unroll
    for (int off = 16; off > 0; off >>= 1) {
        float od = __shfl_down_sync(0xffffffffu, bd, off);
        int   oi = __shfl_down_sync(0xffffffffu, bi, off);
        if (od < bd || (od == bd && oi < bi)) { bd = od; bi = oi; }
    }
    int nn = __shfl_sync(0xffffffffu, bi, 0);

    // gather enc feature (warp-coalesced, 256 floats)
    size_t rb = (size_t)m*K_CLK1;
    const float* feat = enc_features + ((size_t)b*NPTS + nn)*CDIM;
    #pragma unroll
    for (int k = 0; k < CDIM/32; k++)
        g_Xclick[rb + lane + 32*k] = __float2half(feat[lane + 32*k]);

    // fourier pos emb (128 dims per click)
    float x0 = (qx - pc_min[b*3+0]) / (pc_max[b*3+0] - pc_min[b*3+0]);
    float y0 = (qy - pc_min[b*3+1]) / (pc_max[b*3+1] - pc_min[b*3+1]);
    float z0 = (qz - pc_min[b*3+2]) / (pc_max[b*3+2] - pc_min[b*3+2]);
    const float twopi = 6.283185307179586f;
    #pragma unroll
    for (int k = 0; k < 128/32; k++) {
        int d = lane + 32*k;
        float proj = (x0*twopi)*gauss_B[d] + (y0*twopi)*gauss_B[128+d] + (z0*twopi)*gauss_B[256+d];
        g_Xclick[rb + CDIM + d]       = __float2half(sinf(proj));
        g_Xclick[rb + CDIM + 128 + d] = __float2half(cosf(proj));
    }
}

// ---------------- weight conversion: W[K,N] fp32 -> Wh[N,K] fp16 ----------------
__global__ __launch_bounds__(256) void conv_weight_kernel(
    const float* __restrict__ W, __half* __restrict__ B2, int K, int N) {
    __shared__ float t[32][33];
    int n0 = blockIdx.x * 32, k0 = blockIdx.y * 32;
    int tx = threadIdx.x, ty = threadIdx.y;   // block (32,8)
    #pragma unroll
    for (int j = 0; j < 4; j++) {
        int k = k0 + ty + j*8;
        t[ty + j*8][tx] = W[(size_t)k*N + n0 + tx];
    }
    __syncthreads();
    #pragma unroll
    for (int j = 0; j < 4; j++) {
        int n = n0 + ty + j*8;
        int k = k0 + tx;
        B2[(size_t)n*K + k] = __float2half(t[tx][ty + j*8]);
    }
}

// ---------------- HMMA fp16 GEMM ----------------
// D[M,N] = A[M,K] x B[N,K]^T; CTA tile 128x256, warp tile 64x64 (2x4 warps),
// BK=64, 3-stage cp.async pipeline, 1 CTA/SM.
// mode 0: relu(d+bias) -> fp16 into outB [M,QHD]
// mode 1: d+bias -> outF + m*6144 + (m>>6)*BOX_HALF
// mode 2: same + BOX_HALF
#define BM 128
#define BN 256
#define A_STAGE 16384          // 128 x 64 fp16
#define B_STAGE 32768          // 256 x 64 fp16
#define STAGE_BYTES (A_STAGE + B_STAGE)   // 49152
#define OFF_STAGE 1024
#define GEMM_SMEM (OFF_STAGE + 3*STAGE_BYTES)   // 148480

static __device__ __forceinline__ void load_chunk(
    const __half* A2, const __half* B2, int K,
    int bm, int bn, int c, uint32_t sbase, int stage)
{
    int t = threadIdx.x;
    uint32_t stA = sbase + OFF_STAGE + stage*STAGE_BYTES;
    uint32_t stB = stA + A_STAGE;
    // A: 128 rows x 128B = 1024 16B-units; 4 per thread
    #pragma unroll
    for (int i = 0; i < 4; i++) {
        int u = t + 256*i;
        int r = u >> 3, c16 = u & 7;
        uint32_t off = (uint32_t)r*128 + (uint32_t)((c16 ^ (r & 7)) << 4);
        CPA16(stA + off, (const char*)(A2 + (size_t)(bm + r)*K + c*64) + (c16 << 4));
    }
    // B: 256 rows x 128B = 2048 16B-units; 8 per thread
    #pragma unroll
    for (int i = 0; i < 8; i++) {
        int u = t + 256*i;
        int r = u >> 3, c16 = u & 7;
        uint32_t off = (uint32_t)r*128 + (uint32_t)((c16 ^ (r & 7)) << 4);
        CPA16(stB + off, (const char*)(B2 + (size_t)(bn + r)*K + c*64) + (c16 << 4));
    }
}

__global__ __launch_bounds__(256, 1) void gemm_hmma_kernel(
    const __half* A0, const __half* B0, const float* bias0,
    const __half* A1, const __half* B1, const float* bias1,
    int k0_, int k1_, int mode0_, int mode1_,
    float* outF, __half* outB0, __half* outB1)
{
    extern __shared__ char smem[];
    const int z = blockIdx.z;
    const __half* A2 = z ? A1 : A0;
    const __half* B2 = z ? B1 : B0;
    const float* bias = z ? bias1 : bias0;
    __half* outB = z ? outB1 : outB0;
    const int K = z ? k1_ : k0_;
    const int mode = z ? mode1_ : mode0_;
    const int bm = blockIdx.y * BM, bn = blockIdx.x * BN;
    const int tid = threadIdx.x, wid = tid >> 5, lane = tid & 31;
    const int warp_m = wid >> 2, warp_n = wid & 3;   // 2 x 4 warps, 64x64 each
    uint32_t sbase = smem_u32(smem);
    float* sBias = (float*)smem;
    sBias[tid] = bias[bn + tid];

    float acc[4][8][4];
    #pragma unroll
    for (int mi = 0; mi < 4; mi++)
        #pragma unroll
        for (int nj = 0; nj < 8; nj++)
            #pragma unroll
            for (int e = 0; e < 4; e++) acc[mi][nj][e] = 0.0f;

    const int nch = K >> 6;
    load_chunk(A2, B2, K, bm, bn, 0, sbase, 0); CPA_COMMIT();
    load_chunk(A2, B2, K, bm, bn, 1, sbase, 1); CPA_COMMIT();
    load_chunk(A2, B2, K, bm, bn, 2, sbase, 2); CPA_COMMIT();

    const int lane15 = lane & 15, s7 = lane & 7, hic = lane >> 4;

    for (int c = 0; c < nch; c++) {
        int s = c - (c/3)*3;
        if (c + 3 < nch) { asm volatile("cp.async.wait_group 2;\n" ::: "memory"); }
        else             { asm volatile("cp.async.wait_group 0;\n" ::: "memory"); }
        __syncthreads();

        uint32_t stA = sbase + OFF_STAGE + s*STAGE_BYTES;
        uint32_t stB = stA + A_STAGE;
        uint32_t aBase[4], bBase[4];
        #pragma unroll
        for (int mi = 0; mi < 4; mi++)
            aBase[mi] = stA + (uint32_t)(warp_m*64 + mi*16 + lane15) * 128;
        #pragma unroll
        for (int nt = 0; nt < 4; nt++)
            bBase[nt] = stB + (uint32_t)(warp_n*64 + nt*16 + lane15) * 128;

        #pragma unroll
        for (int ks = 0; ks < 4; ks++) {
            uint32_t coff = (uint32_t)(((2*ks + hic) ^ s7) << 4);
            uint32_t afr[4][4], bfr[4][4];
            #pragma unroll
            for (int mi = 0; mi < 4; mi++) LDMX4(afr[mi], aBase[mi] + coff);
            #pragma unroll
            for (int nt = 0; nt < 4; nt++) LDMX4(bfr[nt], bBase[nt] + coff);
            #pragma unroll
            for (int mi = 0; mi < 4; mi++)
                #pragma unroll
                for (int nj = 0; nj < 8; nj++)
                    MMA16816(acc[mi][nj], afr[mi],
                             bfr[nj>>1][nj&1], bfr[nj>>1][2 + (nj&1)]);
        }
        __syncthreads();
        if (c + 3 < nch) {
            load_chunk(A2, B2, K, bm, bn, c + 3, sbase, s);
            CPA_COMMIT();
        }
    }

    // ---- epilogue ----
    #pragma unroll
    for (int mi = 0; mi < 4; mi++) {
        int rr0 = warp_m*64 + mi*16 + (lane >> 2);
        #pragma unroll
        for (int h = 0; h < 2; h++) {
            int m = bm + rr0 + 8*h;
            size_t rowbase;
            if (mode == 0) rowbase = (size_t)m * K_G2;
            else {
                rowbase = (size_t)m * NOUT + (size_t)(m >> 6) * BOX_HALF;
                if (mode == 2) rowbase += BOX_HALF;
            }
            #pragma unroll
            for (int nj = 0; nj < 8; nj++) {
                int cc = warp_n*64 + nj*8 + 2*(lane & 3);
                float v0 = acc[mi][nj][2*h+0] + sBias[cc];
                float v1 = acc[mi][nj][2*h+1] + sBias[cc+1];
                if (mode == 0) {
                    v0 = fmaxf(v0, 0.0f); v1 = fmaxf(v1, 0.0f);
                    __half2 hp; hp.x = __float2half(v0); hp.y = __float2half(v1);
                    *(__half2*)&outB[rowbase + (size_t)(bn + cc)] = hp;
                } else {
                    float2 v; v.x = v0; v.y = v1;
                    *(float2*)&outF[rowbase + bn + cc] = v;
                }
            }
        }
    }
}

// ---------------- mask tail ----------------
__global__ void mask_fill_kernel(const float* __restrict__ box_qmask,
                                 const float* __restrict__ click_qmask,
                                 float* __restrict__ out) {
    int i = blockIdx.x * blockDim.x + threadIdx.x;
    if (i >= BATCH * (NBQ+NCK) * VQ) return;
    int b = i / ((NBQ+NCK)*VQ);
    int s = i % ((NBQ+NCK)*VQ);
    float v;
    if (s < NBQ*VQ) v = box_qmask[b*NBQ + (s >> 3)];
    else            v = click_qmask[b*NCK + ((s - NBQ*VQ) >> 3)];
    out[FEAT_TOTAL + i] = v;
}

// ---------------- launch ----------------
extern "C" void kernel_launch(void* const* d_in, const int* in_sizes, int n_in,
                              void* d_out, int out_size) {
    const float* sem_cls_logits = (const float*)d_in[0];
    const float* prop_features  = (const float*)d_in[1];
    const float* box_corners    = (const float*)d_in[2];
    const float* enc_xyz        = (const float*)d_in[3];
    const float* enc_features   = (const float*)d_in[4];
    const float* pc_min         = (const float*)d_in[5];
    const float* pc_max         = (const float*)d_in[6];
    const float* box_query      = (const float*)d_in[7];
    const float* box_qmask      = (const float*)d_in[8];
    const float* click_query    = (const float*)d_in[9];
    const float* click_qmask    = (const float*)d_in[10];
    const float* gauss_B        = (const float*)d_in[11];
    const float* box_w1         = (const float*)d_in[12];
    const float* box_b1         = (const float*)d_in[13];
    const float* box_w2         = (const float*)d_in[14];
    const float* box_b2         = (const float*)d_in[15];
    const float* click_w1       = (const float*)d_in[16];
    const float* click_b1       = (const float*)d_in[17];
    const float* click_w2       = (const float*)d_in[18];
    const float* click_b2       = (const float*)d_in[19];
    float* out = (float*)d_out;

    __half *Xb, *Xc, *Hb, *Hc, *Wb1, *Wc1, *Wb2, *Wc2;
    cudaGetSymbolAddress((void**)&Xb,  g_Xbox);
    cudaGetSymbolAddress((void**)&Xc,  g_Xclick);
    cudaGetSymbolAddress((void**)&Hb,  g_Hbox);
    cudaGetSymbolAddress((void**)&Hc,  g_Hclick);
    cudaGetSymbolAddress((void**)&Wb1, g_Wb1);
    cudaGetSymbolAddress((void**)&Wc1, g_Wc1);
    cudaGetSymbolAddress((void**)&Wb2, g_Wb2);
    cudaGetSymbolAddress((void**)&Wc2, g_Wc2);

    cudaFuncSetAttribute(gemm_hmma_kernel,
                         cudaFuncAttributeMaxDynamicSharedMemorySize, GEMM_SMEM);

    // prep
    prep_props_kernel<<<(BATCH*NPROP + 255)/256, 256>>>(sem_cls_logits, box_corners);
    prep_queries_kernel<<<(BATCH*NBQ + 255)/256, 256>>>(box_query);
    box_match_kernel<<<MROWS, 256>>>(prop_features);
    click_prep_kernel<<<BATCH*8, 256>>>(click_query, enc_xyz, enc_features,
                                        pc_min, pc_max, gauss_B);
    // weight conversion (W[K,N] fp32 -> Wh[N,K] fp16)
    {
        dim3 blk(32, 8);
        conv_weight_kernel<<<dim3(QHD/32, CDIM/32),     blk>>>(box_w1,   Wb1, CDIM,   QHD);
        conv_weight_kernel<<<dim3(QHD/32, 2*CDIM/32),   blk>>>(click_w1, Wc1, 2*CDIM, QHD);
        conv_weight_kernel<<<dim3(NOUT/32, QHD/32),     blk>>>(box_w2,   Wb2, QHD,    NOUT);
        conv_weight_kernel<<<dim3(NOUT/32, QHD/32),     blk>>>(click_w2, Wc2, QHD,    NOUT);
    }
    // GEMM1 (both branches): X @ W1 + b1, relu -> H (fp16)
    gemm_hmma_kernel<<<dim3(QHD/BN, MROWS/BM, 2), 256, GEMM_SMEM>>>(
        Xb, Wb1, box_b1, Xc, Wc1, click_b1,
        K_BOX1, K_CLK1, 0, 0, nullptr, Hb, Hc);
    // GEMM2 (both branches): H @ W2 + b2 -> out (interleaved layout)
    gemm_hmma_kernel<<<dim3(NOUT/BN, MROWS/BM, 2), 256, GEMM_SMEM>>>(
        Hb, Wb2, box_b2, Hc, Wc2, click_b2,
        K_G2, K_G2, 1, 2, out, nullptr, nullptr);

    mask_fill_kernel<<<(BATCH*(NBQ+NCK)*VQ + 255)/256, 256>>>(box_qmask, click_qmask, out);
}

// round 13
// speedup vs baseline: 1.5609x; 1.0060x over previous
#include <cuda_runtime.h>
#include <cuda_fp16.h>
#include <stdint.h>
#include <math.h>

// ---------------- problem constants ----------------
#define BATCH 32
#define NPROP 256
#define NCLS  19
#define NPTS  4096
#define NBQ   64
#define NCK   64
#define CDIM  256
#define QHD   768
#define VQ    8
#define NOUT  (VQ*QHD)                 // 6144
#define MROWS (BATCH*NBQ)              // 2048
#define FEAT_TOTAL ((size_t)BATCH*(NBQ+NCK)*VQ*QHD)
#define BOX_HALF   (NBQ*VQ*QHD)        // 393216

// pure fp16 K extents
#define K_BOX1  CDIM          // 256
#define K_CLK1  (2*CDIM)      // 512
#define K_G2    QHD           // 768

// ---------------- scratch ----------------
__device__ float g_mnp[BATCH*NPROP*3];
__device__ float g_mxp[BATCH*NPROP*3];
__device__ float g_volp[BATCH*NPROP];
__device__ float g_maskp[BATCH*NPROP];
__device__ float g_mnq[BATCH*NBQ*3];
__device__ float g_mxq[BATCH*NBQ*3];
__device__ float g_volq[BATCH*NBQ];

__device__ __align__(128) __half g_Xbox  [(size_t)MROWS*K_BOX1];
__device__ __align__(128) __half g_Xclick[(size_t)MROWS*K_CLK1];
__device__ __align__(128) __half g_Hbox  [(size_t)MROWS*K_G2];
__device__ __align__(128) __half g_Hclick[(size_t)MROWS*K_G2];
__device__ __align__(128) __half g_Wb1[(size_t)QHD*CDIM];
__device__ __align__(128) __half g_Wc1[(size_t)QHD*2*CDIM];
__device__ __align__(128) __half g_Wb2[(size_t)NOUT*QHD];
__device__ __align__(128) __half g_Wc2[(size_t)NOUT*QHD];

// ---------------- helpers ----------------
static __device__ __forceinline__ uint32_t smem_u32(const void* p) {
    uint32_t a;
    asm("{ .reg .u64 t; cvta.to.shared.u64 t, %1; cvt.u32.u64 %0, t; }" : "=r"(a) : "l"(p));
    return a;
}
#define CPA16(s, g) asm volatile("cp.async.cg.shared.global [%0], [%1], 16;\n" :: "r"(s), "l"(g))
#define CPA_COMMIT() asm volatile("cp.async.commit_group;\n" ::: "memory")

#define LDMX4(r, a) \
    asm volatile("ldmatrix.sync.aligned.m8n8.x4.shared.b16 {%0,%1,%2,%3}, [%4];" \
        : "=r"((r)[0]), "=r"((r)[1]), "=r"((r)[2]), "=r"((r)[3]) : "r"(a))

#define MMA16816(d, a, b0_, b1_) \
    asm volatile("mma.sync.aligned.m16n8k16.row.col.f32.f16.f16.f32 " \
        "{%0,%1,%2,%3}, {%4,%5,%6,%7}, {%8,%9}, {%0,%1,%2,%3};" \
        : "+f"((d)[0]), "+f"((d)[1]), "+f"((d)[2]), "+f"((d)[3]) \
        : "r"((a)[0]), "r"((a)[1]), "r"((a)[2]), "r"((a)[3]), "r"(b0_), "r"(b1_))

// ---------------- prep kernels ----------------
__global__ void prep_props_kernel(const float* __restrict__ logits,
                                  const float* __restrict__ corners) {
    int i = blockIdx.x * blockDim.x + threadIdx.x;
    if (i >= BATCH*NPROP) return;
    const float* lg = logits + (size_t)i*NCLS;
    int am = 0; float best = lg[0];
    #pragma unroll
    for (int c = 1; c < NCLS; c++) { float v = lg[c]; if (v > best) { best = v; am = c; } }
    g_maskp[i] = (am != NCLS-1) ? 1.0f : 0.0f;
    const float* cr = corners + (size_t)i*24;
    float mn[3] = {cr[0], cr[1], cr[2]};
    float mx[3] = {cr[0], cr[1], cr[2]};
    #pragma unroll
    for (int k = 1; k < 8; k++)
        #pragma unroll
        for (int d = 0; d < 3; d++) {
            float v = cr[k*3+d];
            mn[d] = fminf(mn[d], v); mx[d] = fmaxf(mx[d], v);
        }
    float vol = 1.0f;
    #pragma unroll
    for (int d = 0; d < 3; d++) {
        g_mnp[i*3+d] = mn[d]; g_mxp[i*3+d] = mx[d];
        vol *= (mx[d] - mn[d]);
    }
    g_volp[i] = vol;
}

__global__ void prep_queries_kernel(const float* __restrict__ box_query) {
    int i = blockIdx.x * blockDim.x + threadIdx.x;
    if (i >= BATCH*NBQ) return;
    const float* cr = box_query + (size_t)i*24;
    float mn[3] = {cr[0], cr[1], cr[2]};
    float mx[3] = {cr[0], cr[1], cr[2]};
    #pragma unroll
    for (int k = 1; k < 8; k++)
        #pragma unroll
        for (int d = 0; d < 3; d++) {
            float v = cr[k*3+d];
            mn[d] = fminf(mn[d], v); mx[d] = fmaxf(mx[d], v);
        }
    float vol = 1.0f;
    #pragma unroll
    for (int d = 0; d < 3; d++) {
        g_mnq[i*3+d] = mn[d]; g_mxq[i*3+d] = mx[d];
        vol *= (mx[d] - mn[d]);
    }
    g_volq[i] = vol;
}

__global__ __launch_bounds__(256) void box_match_kernel(const float* __restrict__ prop_features) {
    int m = blockIdx.x;
    int b = m >> 6;
    int tid = threadIdx.x;
    float mnq0 = g_mnq[m*3+0], mnq1 = g_mnq[m*3+1], mnq2 = g_mnq[m*3+2];
    float mxq0 = g_mxq[m*3+0], mxq1 = g_mxq[m*3+1], mxq2 = g_mxq[m*3+2];
    float volq = g_volq[m];
    int pi = b*NPROP + tid;
    float i0 = fmaxf(fminf(mxq0, g_mxp[pi*3+0]) - fmaxf(mnq0, g_mnp[pi*3+0]), 0.0f);
    float i1 = fmaxf(fminf(mxq1, g_mxp[pi*3+1]) - fmaxf(mnq1, g_mnp[pi*3+1]), 0.0f);
    float i2 = fmaxf(fminf(mxq2, g_mxp[pi*3+2]) - fmaxf(mnq2, g_mnp[pi*3+2]), 0.0f);
    float inter = i0*i1*i2;
    float iou = inter / (volq + g_volp[pi] - inter + 1e-8f);
    iou *= g_maskp[pi];

    __shared__ float sv[256];
    __shared__ int   si[256];
    sv[tid] = iou; si[tid] = tid;
    __syncthreads();
    #pragma unroll
    for (int off = 128; off > 0; off >>= 1) {
        if (tid < off) {
            float v2 = sv[tid+off]; int j2 = si[tid+off];
            if (v2 > sv[tid] || (v2 == sv[tid] && j2 < si[tid])) { sv[tid] = v2; si[tid] = j2; }
        }
        __syncthreads();
    }
    int idx = si[0];
    float v = prop_features[((size_t)b*NPROP + idx)*CDIM + tid];
    g_Xbox[(size_t)m*K_BOX1 + tid] = __float2half(v);
}

__global__ __launch_bounds__(256) void click_prep_kernel(
    const float* __restrict__ click_query, const float* __restrict__ enc_xyz,
    const float* __restrict__ enc_features, const float* __restrict__ pc_min,
    const float* __restrict__ pc_max, const float* __restrict__ gauss_B) {
    int m = blockIdx.x;
    int b = m >> 6;
    int tid = threadIdx.x;
    float qx = click_query[m*3+0], qy = click_query[m*3+1], qz = click_query[m*3+2];

    const float* xyz = enc_xyz + (size_t)b*NPTS*3;
    float bestd = 3.4e38f; int besti = 0;
    for (int p = tid; p < NPTS; p += 256) {
        float dx = qx - xyz[p*3+0];
        float dy = qy - xyz[p*3+1];
        float dz = qz - xyz[p*3+2];
        float d2 = dx*dx + dy*dy + dz*dz;
        if (d2 < bestd) { bestd = d2; besti = p; }
    }
    __shared__ float sv[256];
    __shared__ int   si[256];
    sv[tid] = bestd; si[tid] = besti;
    __syncthreads();
    #pragma unroll
    for (int off = 128; off > 0; off >>= 1) {
        if (tid < off) {
            float v2 = sv[tid+off]; int j2 = si[tid+off];
            if (v2 < sv[tid] || (v2 == sv[tid] && j2 < si[tid])) { sv[tid] = v2; si[tid] = j2; }
        }
        __syncthreads();
    }
    int nn = si[0];
    size_t rb = (size_t)m*K_CLK1;
    g_Xclick[rb + tid] = __float2half(enc_features[((size_t)b*NPTS + nn)*CDIM + tid]);
    if (tid < 128) {
        float x0 = (qx - pc_min[b*3+0]) / (pc_max[b*3+0] - pc_min[b*3+0]);
        float y0 = (qy - pc_min[b*3+1]) / (pc_max[b*3+1] - pc_min[b*3+1]);
        float z0 = (qz - pc_min[b*3+2]) / (pc_max[b*3+2] - pc_min[b*3+2]);
        const float twopi = 6.283185307179586f;
        float proj = (x0*twopi)*gauss_B[tid] + (y0*twopi)*gauss_B[128+tid] + (z0*twopi)*gauss_B[256+tid];
        g_Xclick[rb + CDIM + tid]       = __float2half(sinf(proj));
        g_Xclick[rb + CDIM + 128 + tid] = __float2half(cosf(proj));
    }
}

// ---------------- weight conversion: W[K,N] fp32 -> Wh[N,K] fp16 ----------------
__global__ __launch_bounds__(256) void conv_weight_kernel(
    const float* __restrict__ W, __half* __restrict__ B2, int K, int N) {
    __shared__ float t[32][33];
    int n0 = blockIdx.x * 32, k0 = blockIdx.y * 32;
    int tx = threadIdx.x, ty = threadIdx.y;   // block (32,8)
    #pragma unroll
    for (int j = 0; j < 4; j++) {
        int k = k0 + ty + j*8;
        t[ty + j*8][tx] = W[(size_t)k*N + n0 + tx];
    }
    __syncthreads();
    #pragma unroll
    for (int j = 0; j < 4; j++) {
        int n = n0 + ty + j*8;
        int k = k0 + tx;
        B2[(size_t)n*K + k] = __float2half(t[tx][ty + j*8]);
    }
}

// ================= GEMM1: BN=128 kernel (verbatim R8 structure) =================
// CTA tile 128x128, warp tile 64x32 (2x4 warps), BK=64, 3-stage, 2 CTAs/SM.
#define BM 128
#define G1_STAGE_BYTES 32768      // A 16KB + B 16KB
#define G1_OFF_STAGE 512
#define GEMM1_SMEM (G1_OFF_STAGE + 3*G1_STAGE_BYTES)   // 98816

static __device__ __forceinline__ void load_chunk1(
    const __half* A2, const __half* B2, int K,
    int bm, int bn, int c, uint32_t sbase, int stage)
{
    int t = threadIdx.x;
    int r = t >> 1;              // 0..127
    int c0 = (t & 1) * 4;        // 0 or 4
    uint32_t stA = sbase + G1_OFF_STAGE + stage*G1_STAGE_BYTES;
    uint32_t stB = stA + 16384;
    const char* ga = (const char*)(A2 + (size_t)(bm + r)*K + c*64);
    const char* gb = (const char*)(B2 + (size_t)(bn + r)*K + c*64);
    uint32_t rowoff = (uint32_t)r * 128;
    int sw = r & 7;
    #pragma unroll
    for (int i = 0; i < 4; i++) {
        int ch = c0 + i;
        uint32_t off = rowoff + (uint32_t)((ch ^ sw) << 4);
        CPA16(stA + off, ga + (ch << 4));
        CPA16(stB + off, gb + (ch << 4));
    }
}

__global__ __launch_bounds__(256, 2) void gemm1_hmma_kernel(
    const __half* A0, const __half* B0, const float* bias0,
    const __half* A1, const __half* B1, const float* bias1,
    int k0_, int k1_, __half* outB0, __half* outB1)
{
    extern __shared__ char smem[];
    const int z = blockIdx.z;
    const __half* A2 = z ? A1 : A0;
    const __half* B2 = z ? B1 : B0;
    const float* bias = z ? bias1 : bias0;
    __half* outB = z ? outB1 : outB0;
    const int K = z ? k1_ : k0_;
    const int bm = blockIdx.y * BM, bn = blockIdx.x * 128;
    const int tid = threadIdx.x, wid = tid >> 5, lane = tid & 31;
    const int warp_m = wid >> 2, warp_n = wid & 3;
    uint32_t sbase = smem_u32(smem);
    float* sBias = (float*)smem;
    if (tid < 128) sBias[tid] = bias[bn + tid];

    float acc[4][4][4];
    #pragma unroll
    for (int mi = 0; mi < 4; mi++)
        #pragma unroll
        for (int nj = 0; nj < 4; nj++)
            #pragma unroll
            for (int e = 0; e < 4; e++) acc[mi][nj][e] = 0.0f;

    const int nch = K >> 6;
    load_chunk1(A2, B2, K, bm, bn, 0, sbase, 0); CPA_COMMIT();
    load_chunk1(A2, B2, K, bm, bn, 1, sbase, 1); CPA_COMMIT();
    load_chunk1(A2, B2, K, bm, bn, 2, sbase, 2); CPA_COMMIT();

    const int lane15 = lane & 15, s7 = lane & 7, hic = lane >> 4;

    for (int c = 0; c < nch; c++) {
        int s = c - (c/3)*3;
        if (c + 3 < nch) { asm volatile("cp.async.wait_group 2;\n" ::: "memory"); }
        else             { asm volatile("cp.async.wait_group 0;\n" ::: "memory"); }
        __syncthreads();

        uint32_t stA = sbase + G1_OFF_STAGE + s*G1_STAGE_BYTES;
        uint32_t stB = stA + 16384;
        uint32_t aBase[4], bBase[2];
        #pragma unroll
        for (int mi = 0; mi < 4; mi++)
            aBase[mi] = stA + (uint32_t)(warp_m*64 + mi*16 + lane15) * 128;
        #pragma unroll
        for (int nt = 0; nt < 2; nt++)
            bBase[nt] = stB + (uint32_t)(warp_n*32 + nt*16 + lane15) * 128;

        #pragma unroll
        for (int ks = 0; ks < 4; ks++) {
            uint32_t coff = (uint32_t)(((2*ks + hic) ^ s7) << 4);
            uint32_t afr[4][4], bfr[2][4];
            #pragma unroll
            for (int mi = 0; mi < 4; mi++) LDMX4(afr[mi], aBase[mi] + coff);
            #pragma unroll
            for (int nt = 0; nt < 2; nt++) LDMX4(bfr[nt], bBase[nt] + coff);
            #pragma unroll
            for (int mi = 0; mi < 4; mi++)
                #pragma unroll
                for (int nj = 0; nj < 4; nj++)
                    MMA16816(acc[mi][nj], afr[mi],
                             bfr[nj>>1][nj&1], bfr[nj>>1][2 + (nj&1)]);
        }
        __syncthreads();
        if (c + 3 < nch) {
            load_chunk1(A2, B2, K, bm, bn, c + 3, sbase, s);
            CPA_COMMIT();
        }
    }

    // epilogue: relu(d+bias) -> fp16 H
    #pragma unroll
    for (int mi = 0; mi < 4; mi++) {
        int rr0 = warp_m*64 + mi*16 + (lane >> 2);
        #pragma unroll
        for (int h = 0; h < 2; h++) {
            int m = bm + rr0 + 8*h;
            size_t rowbase = (size_t)m * K_G2;
            #pragma unroll
            for (int nj = 0; nj < 4; nj++) {
                int cc = warp_n*32 + nj*8 + 2*(lane & 3);
                float v0 = fmaxf(acc[mi][nj][2*h+0] + sBias[cc],   0.0f);
                float v1 = fmaxf(acc[mi][nj][2*h+1] + sBias[cc+1], 0.0f);
                __half2 hp; hp.x = __float2half(v0); hp.y = __float2half(v1);
                *(__half2*)&outB[rowbase + (size_t)(bn + cc)] = hp;
            }
        }
    }
}

// ================= GEMM2: BN=256 kernel (verbatim R9) =================
#define BN 256
#define A_STAGE 16384          // 128 x 64 fp16
#define B_STAGE 32768          // 256 x 64 fp16
#define STAGE_BYTES (A_STAGE + B_STAGE)   // 49152
#define OFF_STAGE 1024
#define GEMM_SMEM (OFF_STAGE + 3*STAGE_BYTES)   // 148480

static __device__ __forceinline__ void load_chunk(
    const __half* A2, const __half* B2, int K,
    int bm, int bn, int c, uint32_t sbase, int stage)
{
    int t = threadIdx.x;
    uint32_t stA = sbase + OFF_STAGE + stage*STAGE_BYTES;
    uint32_t stB = stA + A_STAGE;
    #pragma unroll
    for (int i = 0; i < 4; i++) {
        int u = t + 256*i;
        int r = u >> 3, c16 = u & 7;
        uint32_t off = (uint32_t)r*128 + (uint32_t)((c16 ^ (r & 7)) << 4);
        CPA16(stA + off, (const char*)(A2 + (size_t)(bm + r)*K + c*64) + (c16 << 4));
    }
    #pragma unroll
    for (int i = 0; i < 8; i++) {
        int u = t + 256*i;
        int r = u >> 3, c16 = u & 7;
        uint32_t off = (uint32_t)r*128 + (uint32_t)((c16 ^ (r & 7)) << 4);
        CPA16(stB + off, (const char*)(B2 + (size_t)(bn + r)*K + c*64) + (c16 << 4));
    }
}

__global__ __launch_bounds__(256, 1) void gemm_hmma_kernel(
    const __half* A0, const __half* B0, const float* bias0,
    const __half* A1, const __half* B1, const float* bias1,
    int k0_, int k1_, int mode0_, int mode1_,
    float* outF)
{
    extern __shared__ char smem[];
    const int z = blockIdx.z;
    const __half* A2 = z ? A1 : A0;
    const __half* B2 = z ? B1 : B0;
    const float* bias = z ? bias1 : bias0;
    const int K = z ? k1_ : k0_;
    const int mode = z ? mode1_ : mode0_;
    const int bm = blockIdx.y * BM, bn = blockIdx.x * BN;
    const int tid = threadIdx.x, wid = tid >> 5, lane = tid & 31;
    const int warp_m = wid >> 2, warp_n = wid & 3;   // 2 x 4 warps, 64x64 each
    uint32_t sbase = smem_u32(smem);
    float* sBias = (float*)smem;
    sBias[tid] = bias[bn + tid];

    float acc[4][8][4];
    #pragma unroll
    for (int mi = 0; mi < 4; mi++)
        #pragma unroll
        for (int nj = 0; nj < 8; nj++)
            #pragma unroll
            for (int e = 0; e < 4; e++) acc[mi][nj][e] = 0.0f;

    const int nch = K >> 6;
    load_chunk(A2, B2, K, bm, bn, 0, sbase, 0); CPA_COMMIT();
    load_chunk(A2, B2, K, bm, bn, 1, sbase, 1); CPA_COMMIT();
    load_chunk(A2, B2, K, bm, bn, 2, sbase, 2); CPA_COMMIT();

    const int lane15 = lane & 15, s7 = lane & 7, hic = lane >> 4;

    for (int c = 0; c < nch; c++) {
        int s = c - (c/3)*3;
        if (c + 3 < nch) { asm volatile("cp.async.wait_group 2;\n" ::: "memory"); }
        else             { asm volatile("cp.async.wait_group 0;\n" ::: "memory"); }
        __syncthreads();

        uint32_t stA = sbase + OFF_STAGE + s*STAGE_BYTES;
        uint32_t stB = stA + A_STAGE;
        uint32_t aBase[4], bBase[4];
        #pragma unroll
        for (int mi = 0; mi < 4; mi++)
            aBase[mi] = stA + (uint32_t)(warp_m*64 + mi*16 + lane15) * 128;
        #pragma unroll
        for (int nt = 0; nt < 4; nt++)
            bBase[nt] = stB + (uint32_t)(warp_n*64 + nt*16 + lane15) * 128;

        #pragma unroll
        for (int ks = 0; ks < 4; ks++) {
            uint32_t coff = (uint32_t)(((2*ks + hic) ^ s7) << 4);
            uint32_t afr[4][4], bfr[4][4];
            #pragma unroll
            for (int mi = 0; mi < 4; mi++) LDMX4(afr[mi], aBase[mi] + coff);
            #pragma unroll
            for (int nt = 0; nt < 4; nt++) LDMX4(bfr[nt], bBase[nt] + coff);
            #pragma unroll
            for (int mi = 0; mi < 4; mi++)
                #pragma unroll
                for (int nj = 0; nj < 8; nj++)
                    MMA16816(acc[mi][nj], afr[mi],
                             bfr[nj>>1][nj&1], bfr[nj>>1][2 + (nj&1)]);
        }
        __syncthreads();
        if (c + 3 < nch) {
            load_chunk(A2, B2, K, bm, bn, c + 3, sbase, s);
            CPA_COMMIT();
        }
    }

    // ---- epilogue: d+bias -> interleaved fp32 output ----
    #pragma unroll
    for (int mi = 0; mi < 4; mi++) {
        int rr0 = warp_m*64 + mi*16 + (lane >> 2);
        #pragma unroll
        for (int h = 0; h < 2; h++) {
            int m = bm + rr0 + 8*h;
            size_t rowbase = (size_t)m * NOUT + (size_t)(m >> 6) * BOX_HALF;
            if (mode == 2) rowbase += BOX_HALF;
            #pragma unroll
            for (int nj = 0; nj < 8; nj++) {
                int cc = warp_n*64 + nj*8 + 2*(lane & 3);
                float2 v;
                v.x = acc[mi][nj][2*h+0] + sBias[cc];
                v.y = acc[mi][nj][2*h+1] + sBias[cc+1];
                *(float2*)&outF[rowbase + bn + cc] = v;
            }
        }
    }
}

// ---------------- mask tail ----------------
__global__ void mask_fill_kernel(const float* __restrict__ box_qmask,
                                 const float* __restrict__ click_qmask,
                                 float* __restrict__ out) {
    int i = blockIdx.x * blockDim.x + threadIdx.x;
    if (i >= BATCH * (NBQ+NCK) * VQ) return;
    int b = i / ((NBQ+NCK)*VQ);
    int s = i % ((NBQ+NCK)*VQ);
    float v;
    if (s < NBQ*VQ) v = box_qmask[b*NBQ + (s >> 3)];
    else            v = click_qmask[b*NCK + ((s - NBQ*VQ) >> 3)];
    out[FEAT_TOTAL + i] = v;
}

// ---------------- launch ----------------
extern "C" void kernel_launch(void* const* d_in, const int* in_sizes, int n_in,
                              void* d_out, int out_size) {
    const float* sem_cls_logits = (const float*)d_in[0];
    const float* prop_features  = (const float*)d_in[1];
    const float* box_corners    = (const float*)d_in[2];
    const float* enc_xyz        = (const float*)d_in[3];
    const float* enc_features   = (const float*)d_in[4];
    const float* pc_min         = (const float*)d_in[5];
    const float* pc_max         = (const float*)d_in[6];
    const float* box_query      = (const float*)d_in[7];
    const float* box_qmask      = (const float*)d_in[8];
    const float* click_query    = (const float*)d_in[9];
    const float* click_qmask    = (const float*)d_in[10];
    const float* gauss_B        = (const float*)d_in[11];
    const float* box_w1         = (const float*)d_in[12];
    const float* box_b1         = (const float*)d_in[13];
    const float* box_w2         = (const float*)d_in[14];
    const float* box_b2         = (const float*)d_in[15];
    const float* click_w1       = (const float*)d_in[16];
    const float* click_b1       = (const float*)d_in[17];
    const float* click_w2       = (const float*)d_in[18];
    const float* click_b2       = (const float*)d_in[19];
    float* out = (float*)d_out;

    __half *Xb, *Xc, *Hb, *Hc, *Wb1, *Wc1, *Wb2, *Wc2;
    cudaGetSymbolAddress((void**)&Xb,  g_Xbox);
    cudaGetSymbolAddress((void**)&Xc,  g_Xclick);
    cudaGetSymbolAddress((void**)&Hb,  g_Hbox);
    cudaGetSymbolAddress((void**)&Hc,  g_Hclick);
    cudaGetSymbolAddress((void**)&Wb1, g_Wb1);
    cudaGetSymbolAddress((void**)&Wc1, g_Wc1);
    cudaGetSymbolAddress((void**)&Wb2, g_Wb2);
    cudaGetSymbolAddress((void**)&Wc2, g_Wc2);

    cudaFuncSetAttribute(gemm1_hmma_kernel,
                         cudaFuncAttributeMaxDynamicSharedMemorySize, GEMM1_SMEM);
    cudaFuncSetAttribute(gemm_hmma_kernel,
                         cudaFuncAttributeMaxDynamicSharedMemorySize, GEMM_SMEM);

    // prep
    prep_props_kernel<<<(BATCH*NPROP + 255)/256, 256>>>(sem_cls_logits, box_corners);
    prep_queries_kernel<<<(BATCH*NBQ + 255)/256, 256>>>(box_query);
    box_match_kernel<<<MROWS, 256>>>(prop_features);
    click_prep_kernel<<<MROWS, 256>>>(click_query, enc_xyz, enc_features,
                                      pc_min, pc_max, gauss_B);
    // weight conversion (W[K,N] fp32 -> Wh[N,K] fp16)
    {
        dim3 blk(32, 8);
        conv_weight_kernel<<<dim3(QHD/32, CDIM/32),     blk>>>(box_w1,   Wb1, CDIM,   QHD);
        conv_weight_kernel<<<dim3(QHD/32, 2*CDIM/32),   blk>>>(click_w1, Wc1, 2*CDIM, QHD);
        conv_weight_kernel<<<dim3(NOUT/32, QHD/32),     blk>>>(box_w2,   Wb2, QHD,    NOUT);
        conv_weight_kernel<<<dim3(NOUT/32, QHD/32),     blk>>>(click_w2, Wc2, QHD,    NOUT);
    }
    // GEMM1 (both branches): X @ W1 + b1, relu -> H (fp16); BN=128 -> 192 CTAs
    gemm1_hmma_kernel<<<dim3(QHD/128, MROWS/BM, 2), 256, GEMM1_SMEM>>>(
        Xb, Wb1, box_b1, Xc, Wc1, click_b1,
        K_BOX1, K_CLK1, Hb, Hc);
    // GEMM2 (both branches): H @ W2 + b2 -> out (interleaved layout); BN=256
    gemm_hmma_kernel<<<dim3(NOUT/BN, MROWS/BM, 2), 256, GEMM_SMEM>>>(
        Hb, Wb2, box_b2, Hc, Wc2, click_b2,
        K_G2, K_G2, 1, 2, out);

    mask_fill_kernel<<<(BATCH*(NBQ+NCK)*VQ + 255)/256, 256>>>(box_qmask, click_qmask, out);
}

// round 15
// speedup vs baseline: 1.7485x; 1.1202x over previous
#include <cuda_runtime.h>
#include <cuda_fp16.h>
#include <stdint.h>
#include <math.h>

// ---------------- problem constants ----------------
#define BATCH 32
#define NPROP 256
#define NCLS  19
#define NPTS  4096
#define NBQ   64
#define NCK   64
#define CDIM  256
#define QHD   768
#define VQ    8
#define NOUT  (VQ*QHD)                 // 6144
#define MROWS (BATCH*NBQ)              // 2048
#define FEAT_TOTAL ((size_t)BATCH*(NBQ+NCK)*VQ*QHD)
#define BOX_HALF   (NBQ*VQ*QHD)        // 393216

// pure fp16 K extents
#define K_BOX1  CDIM          // 256
#define K_CLK1  (2*CDIM)      // 512
#define K_G2    QHD           // 768

// ---------------- scratch ----------------
__device__ float g_mnp[BATCH*NPROP*3];
__device__ float g_mxp[BATCH*NPROP*3];
__device__ float g_volp[BATCH*NPROP];
__device__ float g_maskp[BATCH*NPROP];
__device__ float g_mnq[BATCH*NBQ*3];
__device__ float g_mxq[BATCH*NBQ*3];
__device__ float g_volq[BATCH*NBQ];

__device__ __align__(128) __half g_Xbox  [(size_t)MROWS*K_BOX1];
__device__ __align__(128) __half g_Xclick[(size_t)MROWS*K_CLK1];
__device__ __align__(128) __half g_Hbox  [(size_t)MROWS*K_G2];
__device__ __align__(128) __half g_Hclick[(size_t)MROWS*K_G2];
__device__ __align__(128) __half g_Wb1[(size_t)QHD*CDIM];
__device__ __align__(128) __half g_Wc1[(size_t)QHD*2*CDIM];
__device__ __align__(128) __half g_Wb2[(size_t)NOUT*QHD];
__device__ __align__(128) __half g_Wc2[(size_t)NOUT*QHD];

// ---------------- helpers ----------------
static __device__ __forceinline__ uint32_t smem_u32(const void* p) {
    uint32_t a;
    asm("{ .reg .u64 t; cvta.to.shared.u64 t, %1; cvt.u32.u64 %0, t; }" : "=r"(a) : "l"(p));
    return a;
}
#define CPA16(s, g) asm volatile("cp.async.cg.shared.global [%0], [%1], 16;\n" :: "r"(s), "l"(g))
#define CPA_COMMIT() asm volatile("cp.async.commit_group;\n" ::: "memory")

#define LDMX4(r, a) \
    asm volatile("ldmatrix.sync.aligned.m8n8.x4.shared.b16 {%0,%1,%2,%3}, [%4];" \
        : "=r"((r)[0]), "=r"((r)[1]), "=r"((r)[2]), "=r"((r)[3]) : "r"(a))

#define MMA16816(d, a, b0_, b1_) \
    asm volatile("mma.sync.aligned.m16n8k16.row.col.f32.f16.f16.f32 " \
        "{%0,%1,%2,%3}, {%4,%5,%6,%7}, {%8,%9}, {%0,%1,%2,%3};" \
        : "+f"((d)[0]), "+f"((d)[1]), "+f"((d)[2]), "+f"((d)[3]) \
        : "r"((a)[0]), "r"((a)[1]), "r"((a)[2]), "r"((a)[3]), "r"(b0_), "r"(b1_))

// ---------------- prep kernels ----------------
__global__ void prep_props_kernel(const float* __restrict__ logits,
                                  const float* __restrict__ corners) {
    int i = blockIdx.x * blockDim.x + threadIdx.x;
    if (i >= BATCH*NPROP) return;
    const float* lg = logits + (size_t)i*NCLS;
    int am = 0; float best = lg[0];
    #pragma unroll
    for (int c = 1; c < NCLS; c++) { float v = lg[c]; if (v > best) { best = v; am = c; } }
    g_maskp[i] = (am != NCLS-1) ? 1.0f : 0.0f;
    const float* cr = corners + (size_t)i*24;
    float mn[3] = {cr[0], cr[1], cr[2]};
    float mx[3] = {cr[0], cr[1], cr[2]};
    #pragma unroll
    for (int k = 1; k < 8; k++)
        #pragma unroll
        for (int d = 0; d < 3; d++) {
            float v = cr[k*3+d];
            mn[d] = fminf(mn[d], v); mx[d] = fmaxf(mx[d], v);
        }
    float vol = 1.0f;
    #pragma unroll
    for (int d = 0; d < 3; d++) {
        g_mnp[i*3+d] = mn[d]; g_mxp[i*3+d] = mx[d];
        vol *= (mx[d] - mn[d]);
    }
    g_volp[i] = vol;
}

__global__ void prep_queries_kernel(const float* __restrict__ box_query) {
    int i = blockIdx.x * blockDim.x + threadIdx.x;
    if (i >= BATCH*NBQ) return;
    const float* cr = box_query + (size_t)i*24;
    float mn[3] = {cr[0], cr[1], cr[2]};
    float mx[3] = {cr[0], cr[1], cr[2]};
    #pragma unroll
    for (int k = 1; k < 8; k++)
        #pragma unroll
        for (int d = 0; d < 3; d++) {
            float v = cr[k*3+d];
            mn[d] = fminf(mn[d], v); mx[d] = fmaxf(mx[d], v);
        }
    float vol = 1.0f;
    #pragma unroll
    for (int d = 0; d < 3; d++) {
        g_mnq[i*3+d] = mn[d]; g_mxq[i*3+d] = mx[d];
        vol *= (mx[d] - mn[d]);
    }
    g_volq[i] = vol;
}

__global__ __launch_bounds__(256) void box_match_kernel(const float* __restrict__ prop_features) {
    int m = blockIdx.x;
    int b = m >> 6;
    int tid = threadIdx.x;
    float mnq0 = g_mnq[m*3+0], mnq1 = g_mnq[m*3+1], mnq2 = g_mnq[m*3+2];
    float mxq0 = g_mxq[m*3+0], mxq1 = g_mxq[m*3+1], mxq2 = g_mxq[m*3+2];
    float volq = g_volq[m];
    int pi = b*NPROP + tid;
    float i0 = fmaxf(fminf(mxq0, g_mxp[pi*3+0]) - fmaxf(mnq0, g_mnp[pi*3+0]), 0.0f);
    float i1 = fmaxf(fminf(mxq1, g_mxp[pi*3+1]) - fmaxf(mnq1, g_mnp[pi*3+1]), 0.0f);
    float i2 = fmaxf(fminf(mxq2, g_mxp[pi*3+2]) - fmaxf(mnq2, g_mnp[pi*3+2]), 0.0f);
    float inter = i0*i1*i2;
    float iou = inter / (volq + g_volp[pi] - inter + 1e-8f);
    iou *= g_maskp[pi];

    __shared__ float sv[256];
    __shared__ int   si[256];
    sv[tid] = iou; si[tid] = tid;
    __syncthreads();
    #pragma unroll
    for (int off = 128; off > 0; off >>= 1) {
        if (tid < off) {
            float v2 = sv[tid+off]; int j2 = si[tid+off];
            if (v2 > sv[tid] || (v2 == sv[tid] && j2 < si[tid])) { sv[tid] = v2; si[tid] = j2; }
        }
        __syncthreads();
    }
    int idx = si[0];
    float v = prop_features[((size_t)b*NPROP + idx)*CDIM + tid];
    g_Xbox[(size_t)m*K_BOX1 + tid] = __float2half(v);
}

__global__ __launch_bounds__(256) void click_prep_kernel(
    const float* __restrict__ click_query, const float* __restrict__ enc_xyz,
    const float* __restrict__ enc_features, const float* __restrict__ pc_min,
    const float* __restrict__ pc_max, const float* __restrict__ gauss_B) {
    int m = blockIdx.x;
    int b = m >> 6;
    int tid = threadIdx.x;
    float qx = click_query[m*3+0], qy = click_query[m*3+1], qz = click_query[m*3+2];

    const float* xyz = enc_xyz + (size_t)b*NPTS*3;
    float bestd = 3.4e38f; int besti = 0;
    for (int p = tid; p < NPTS; p += 256) {
        float dx = qx - xyz[p*3+0];
        float dy = qy - xyz[p*3+1];
        float dz = qz - xyz[p*3+2];
        float d2 = dx*dx + dy*dy + dz*dz;
        if (d2 < bestd) { bestd = d2; besti = p; }
    }
    __shared__ float sv[256];
    __shared__ int   si[256];
    sv[tid] = bestd; si[tid] = besti;
    __syncthreads();
    #pragma unroll
    for (int off = 128; off > 0; off >>= 1) {
        if (tid < off) {
            float v2 = sv[tid+off]; int j2 = si[tid+off];
            if (v2 < sv[tid] || (v2 == sv[tid] && j2 < si[tid])) { sv[tid] = v2; si[tid] = j2; }
        }
        __syncthreads();
    }
    int nn = si[0];
    size_t rb = (size_t)m*K_CLK1;
    g_Xclick[rb + tid] = __float2half(enc_features[((size_t)b*NPTS + nn)*CDIM + tid]);
    if (tid < 128) {
        float x0 = (qx - pc_min[b*3+0]) / (pc_max[b*3+0] - pc_min[b*3+0]);
        float y0 = (qy - pc_min[b*3+1]) / (pc_max[b*3+1] - pc_min[b*3+1]);
        float z0 = (qz - pc_min[b*3+2]) / (pc_max[b*3+2] - pc_min[b*3+2]);
        const float twopi = 6.283185307179586f;
        float proj = (x0*twopi)*gauss_B[tid] + (y0*twopi)*gauss_B[128+tid] + (z0*twopi)*gauss_B[256+tid];
        g_Xclick[rb + CDIM + tid]       = __float2half(sinf(proj));
        g_Xclick[rb + CDIM + 128 + tid] = __float2half(cosf(proj));
    }
}

// ---------------- fused weight conversion: all 4 weights in one launch ----------------
// blockIdx.z selects weight; out-of-range tiles exit early.
__global__ __launch_bounds__(256) void conv_all_kernel(
    const float* __restrict__ w0, __half* __restrict__ o0,   // box_w1  K=256  N=768
    const float* __restrict__ w1, __half* __restrict__ o1,   // click_w1 K=512 N=768
    const float* __restrict__ w2, __half* __restrict__ o2,   // box_w2  K=768  N=6144
    const float* __restrict__ w3, __half* __restrict__ o3)   // click_w2 K=768 N=6144
{
    const float* W; __half* B2; int K, N;
    switch (blockIdx.z) {
        case 0:  W = w0; B2 = o0; K = CDIM;   N = QHD;  break;
        case 1:  W = w1; B2 = o1; K = 2*CDIM; N = QHD;  break;
        case 2:  W = w2; B2 = o2; K = QHD;    N = NOUT; break;
        default: W = w3; B2 = o3; K = QHD;    N = NOUT; break;
    }
    int n0 = blockIdx.x * 32, k0 = blockIdx.y * 32;
    if (n0 >= N || k0 >= K) return;
    __shared__ float t[32][33];
    int tx = threadIdx.x, ty = threadIdx.y;   // block (32,8)
    #pragma unroll
    for (int j = 0; j < 4; j++) {
        int k = k0 + ty + j*8;
        t[ty + j*8][tx] = W[(size_t)k*N + n0 + tx];
    }
    __syncthreads();
    #pragma unroll
    for (int j = 0; j < 4; j++) {
        int n = n0 + ty + j*8;
        int k = k0 + tx;
        B2[(size_t)n*K + k] = __float2half(t[tx][ty + j*8]);
    }
}

// ---------------- HMMA fp16 GEMM ----------------
// D[M,N] = A[M,K] x B[N,K]^T; CTA tile 128x192, warp tile 64x48 (2x4 warps),
// BK=64, 3-stage cp.async pipeline, 1 CTA/SM.
// mode 0: relu(d+bias) -> fp16 into outB [M,QHD]
// mode 1: d+bias -> outF + m*6144 + (m>>6)*BOX_HALF
// mode 2: same + BOX_HALF
#define BM 128
#define BN 192
#define NJ 6                   // 8-col frags per warp (48/8)
#define NT 3                   // 16-row ldmatrix groups per warp
#define A_STAGE 16384          // 128 x 64 fp16
#define B_STAGE 24576          // 192 x 64 fp16
#define STAGE_BYTES (A_STAGE + B_STAGE)   // 40960
#define OFF_STAGE 1024
#define GEMM_SMEM (OFF_STAGE + 3*STAGE_BYTES)   // 123904

static __device__ __forceinline__ void load_chunk(
    const __half* A2, const __half* B2, int K,
    int bm, int bn, int c, uint32_t sbase, int stage)
{
    int t = threadIdx.x;
    uint32_t stA = sbase + OFF_STAGE + stage*STAGE_BYTES;
    uint32_t stB = stA + A_STAGE;
    // A: 128 rows x 128B = 1024 16B-units; 4 per thread
    #pragma unroll
    for (int i = 0; i < 4; i++) {
        int u = t + 256*i;
        int r = u >> 3, c16 = u & 7;
        uint32_t off = (uint32_t)r*128 + (uint32_t)((c16 ^ (r & 7)) << 4);
        CPA16(stA + off, (const char*)(A2 + (size_t)(bm + r)*K + c*64) + (c16 << 4));
    }
    // B: 192 rows x 128B = 1536 16B-units; 6 per thread
    #pragma unroll
    for (int i = 0; i < 6; i++) {
        int u = t + 256*i;
        int r = u >> 3, c16 = u & 7;
        uint32_t off = (uint32_t)r*128 + (uint32_t)((c16 ^ (r & 7)) << 4);
        CPA16(stB + off, (const char*)(B2 + (size_t)(bn + r)*K + c*64) + (c16 << 4));
    }
}

__global__ __launch_bounds__(256, 1) void gemm_hmma_kernel(
    const __half* A0, const __half* B0, const float* bias0,
    const __half* A1, const __half* B1, const float* bias1,
    int k0_, int k1_, int mode0_, int mode1_,
    float* outF, __half* outB0, __half* outB1)
{
    extern __shared__ char smem[];
    const int z = blockIdx.z;
    const __half* A2 = z ? A1 : A0;
    const __half* B2 = z ? B1 : B0;
    const float* bias = z ? bias1 : bias0;
    __half* outB = z ? outB1 : outB0;
    const int K = z ? k1_ : k0_;
    const int mode = z ? mode1_ : mode0_;
    const int bm = blockIdx.y * BM, bn = blockIdx.x * BN;
    const int tid = threadIdx.x, wid = tid >> 5, lane = tid & 31;
    const int warp_m = wid >> 2, warp_n = wid & 3;   // 2 x 4 warps, 64x48 each
    uint32_t sbase = smem_u32(smem);
    float* sBias = (float*)smem;
    if (tid < BN) sBias[tid] = bias[bn + tid];

    float acc[4][NJ][4];
    #pragma unroll
    for (int mi = 0; mi < 4; mi++)
        #pragma unroll
        for (int nj = 0; nj < NJ; nj++)
            #pragma unroll
            for (int e = 0; e < 4; e++) acc[mi][nj][e] = 0.0f;

    const int nch = K >> 6;
    load_chunk(A2, B2, K, bm, bn, 0, sbase, 0); CPA_COMMIT();
    load_chunk(A2, B2, K, bm, bn, 1, sbase, 1); CPA_COMMIT();
    load_chunk(A2, B2, K, bm, bn, 2, sbase, 2); CPA_COMMIT();

    const int lane15 = lane & 15, s7 = lane & 7, hic = lane >> 4;

    for (int c = 0; c < nch; c++) {
        int s = c - (c/3)*3;
        if (c + 3 < nch) { asm volatile("cp.async.wait_group 2;\n" ::: "memory"); }
        else             { asm volatile("cp.async.wait_group 0;\n" ::: "memory"); }
        __syncthreads();

        uint32_t stA = sbase + OFF_STAGE + s*STAGE_BYTES;
        uint32_t stB = stA + A_STAGE;
        uint32_t aBase[4], bBase[NT];
        #pragma unroll
        for (int mi = 0; mi < 4; mi++)
            aBase[mi] = stA + (uint32_t)(warp_m*64 + mi*16 + lane15) * 128;
        #pragma unroll
        for (int nt = 0; nt < NT; nt++)
            bBase[nt] = stB + (uint32_t)(warp_n*48 + nt*16 + lane15) * 128;

        #pragma unroll
        for (int ks = 0; ks < 4; ks++) {
            uint32_t coff = (uint32_t)(((2*ks + hic) ^ s7) << 4);
            uint32_t afr[4][4], bfr[NT][4];
            #pragma unroll
            for (int mi = 0; mi < 4; mi++) LDMX4(afr[mi], aBase[mi] + coff);
            #pragma unroll
            for (int nt = 0; nt < NT; nt++) LDMX4(bfr[nt], bBase[nt] + coff);
            #pragma unroll
            for (int mi = 0; mi < 4; mi++)
                #pragma unroll
                for (int nj = 0; nj < NJ; nj++)
                    MMA16816(acc[mi][nj], afr[mi],
                             bfr[nj>>1][nj&1], bfr[nj>>1][2 + (nj&1)]);
        }
        __syncthreads();
        if (c + 3 < nch) {
            load_chunk(A2, B2, K, bm, bn, c + 3, sbase, s);
            CPA_COMMIT();
        }
    }

    // ---- epilogue ----
    #pragma unroll
    for (int mi = 0; mi < 4; mi++) {
        int rr0 = warp_m*64 + mi*16 + (lane >> 2);
        #pragma unroll
        for (int h = 0; h < 2; h++) {
            int m = bm + rr0 + 8*h;
            size_t rowbase;
            if (mode == 0) rowbase = (size_t)m * K_G2;
            else {
                rowbase = (size_t)m * NOUT + (size_t)(m >> 6) * BOX_HALF;
                if (mode == 2) rowbase += BOX_HALF;
            }
            #pragma unroll
            for (int nj = 0; nj < NJ; nj++) {
                int cc = warp_n*48 + nj*8 + 2*(lane & 3);
                float v0 = acc[mi][nj][2*h+0] + sBias[cc];
                float v1 = acc[mi][nj][2*h+1] + sBias[cc+1];
                if (mode == 0) {
                    v0 = fmaxf(v0, 0.0f); v1 = fmaxf(v1, 0.0f);
                    __half2 hp; hp.x = __float2half(v0); hp.y = __float2half(v1);
                    *(__half2*)&outB[rowbase + (size_t)(bn + cc)] = hp;
                } else {
                    float2 v; v.x = v0; v.y = v1;
                    *(float2*)&outF[rowbase + bn + cc] = v;
                }
            }
        }
    }
}

// ---------------- mask tail ----------------
__global__ void mask_fill_kernel(const float* __restrict__ box_qmask,
                                 const float* __restrict__ click_qmask,
                                 float* __restrict__ out) {
    int i = blockIdx.x * blockDim.x + threadIdx.x;
    if (i >= BATCH * (NBQ+NCK) * VQ) return;
    int b = i / ((NBQ+NCK)*VQ);
    int s = i % ((NBQ+NCK)*VQ);
    float v;
    if (s < NBQ*VQ) v = box_qmask[b*NBQ + (s >> 3)];
    else            v = click_qmask[b*NCK + ((s - NBQ*VQ) >> 3)];
    out[FEAT_TOTAL + i] = v;
}

// ---------------- launch ----------------
extern "C" void kernel_launch(void* const* d_in, const int* in_sizes, int n_in,
                              void* d_out, int out_size) {
    const float* sem_cls_logits = (const float*)d_in[0];
    const float* prop_features  = (const float*)d_in[1];
    const float* box_corners    = (const float*)d_in[2];
    const float* enc_xyz        = (const float*)d_in[3];
    const float* enc_features   = (const float*)d_in[4];
    const float* pc_min         = (const float*)d_in[5];
    const float* pc_max         = (const float*)d_in[6];
    const float* box_query      = (const float*)d_in[7];
    const float* box_qmask      = (const float*)d_in[8];
    const float* click_query    = (const float*)d_in[9];
    const float* click_qmask    = (const float*)d_in[10];
    const float* gauss_B        = (const float*)d_in[11];
    const float* box_w1         = (const float*)d_in[12];
    const float* box_b1         = (const float*)d_in[13];
    const float* box_w2         = (const float*)d_in[14];
    const float* box_b2         = (const float*)d_in[15];
    const float* click_w1       = (const float*)d_in[16];
    const float* click_b1       = (const float*)d_in[17];
    const float* click_w2       = (const float*)d_in[18];
    const float* click_b2       = (const float*)d_in[19];
    float* out = (float*)d_out;

    __half *Xb, *Xc, *Hb, *Hc, *Wb1, *Wc1, *Wb2, *Wc2;
    cudaGetSymbolAddress((void**)&Xb,  g_Xbox);
    cudaGetSymbolAddress((void**)&Xc,  g_Xclick);
    cudaGetSymbolAddress((void**)&Hb,  g_Hbox);
    cudaGetSymbolAddress((void**)&Hc,  g_Hclick);
    cudaGetSymbolAddress((void**)&Wb1, g_Wb1);
    cudaGetSymbolAddress((void**)&Wc1, g_Wc1);
    cudaGetSymbolAddress((void**)&Wb2, g_Wb2);
    cudaGetSymbolAddress((void**)&Wc2, g_Wc2);

    cudaFuncSetAttribute(gemm_hmma_kernel,
                         cudaFuncAttributeMaxDynamicSharedMemorySize, GEMM_SMEM);

    // prep
    prep_props_kernel<<<(BATCH*NPROP + 255)/256, 256>>>(sem_cls_logits, box_corners);
    prep_queries_kernel<<<(BATCH*NBQ + 255)/256, 256>>>(box_query);
    box_match_kernel<<<MROWS, 256>>>(prop_features);
    click_prep_kernel<<<MROWS, 256>>>(click_query, enc_xyz, enc_features,
                                      pc_min, pc_max, gauss_B);
    // fused weight conversion (W[K,N] fp32 -> Wh[N,K] fp16), single launch
    {
        dim3 blk(32, 8);
        dim3 grid(NOUT/32, QHD/32, 4);   // max dims; ragged tiles early-exit
        conv_all_kernel<<<grid, blk>>>(box_w1, Wb1, click_w1, Wc1,
                                       box_w2, Wb2, click_w2, Wc2);
    }
    // GEMM1 (both branches): X @ W1 + b1, relu -> H (fp16); 128 CTAs
    gemm_hmma_kernel<<<dim3(QHD/BN, MROWS/BM, 2), 256, GEMM_SMEM>>>(
        Xb, Wb1, box_b1, Xc, Wc1, click_b1,
        K_BOX1, K_CLK1, 0, 0, nullptr, Hb, Hc);
    // GEMM2 (both branches): H @ W2 + b2 -> out (interleaved layout); 1024 CTAs
    gemm_hmma_kernel<<<dim3(NOUT/BN, MROWS/BM, 2), 256, GEMM_SMEM>>>(
        Hb, Wb2, box_b2, Hc, Wc2, click_b2,
        K_G2, K_G2, 1, 2, out, nullptr, nullptr);

    mask_fill_kernel<<<(BATCH*(NBQ+NCK)*VQ + 255)/256, 256>>>(box_qmask, click_qmask, out);
}

// round 16
// speedup vs baseline: 1.8642x; 1.0662x over previous
#include <cuda_runtime.h>
#include <cuda_fp16.h>
#include <stdint.h>
#include <math.h>

// ---------------- problem constants ----------------
#define BATCH 32
#define NPROP 256
#define NCLS  19
#define NPTS  4096
#define NBQ   64
#define NCK   64
#define CDIM  256
#define QHD   768
#define VQ    8
#define NOUT  (VQ*QHD)                 // 6144
#define MROWS (BATCH*NBQ)              // 2048
#define FEAT_TOTAL ((size_t)BATCH*(NBQ+NCK)*VQ*QHD)
#define BOX_HALF   (NBQ*VQ*QHD)        // 393216

// pure fp16 K extents
#define K_BOX1  CDIM          // 256
#define K_CLK1  (2*CDIM)      // 512
#define K_G2    QHD           // 768

// ---------------- scratch ----------------
__device__ float g_mnp[BATCH*NPROP*3];
__device__ float g_mxp[BATCH*NPROP*3];
__device__ float g_volp[BATCH*NPROP];
__device__ float g_maskp[BATCH*NPROP];
__device__ float g_mnq[BATCH*NBQ*3];
__device__ float g_mxq[BATCH*NBQ*3];
__device__ float g_volq[BATCH*NBQ];

__device__ __align__(128) __half g_Xbox  [(size_t)MROWS*K_BOX1];
__device__ __align__(128) __half g_Xclick[(size_t)MROWS*K_CLK1];
__device__ __align__(128) __half g_Hbox  [(size_t)MROWS*K_G2];
__device__ __align__(128) __half g_Hclick[(size_t)MROWS*K_G2];
__device__ __align__(128) __half g_Wb1[(size_t)QHD*CDIM];
__device__ __align__(128) __half g_Wc1[(size_t)QHD*2*CDIM];
__device__ __align__(128) __half g_Wb2[(size_t)NOUT*QHD];
__device__ __align__(128) __half g_Wc2[(size_t)NOUT*QHD];

// ---------------- helpers ----------------
static __device__ __forceinline__ uint32_t smem_u32(const void* p) {
    uint32_t a;
    asm("{ .reg .u64 t; cvta.to.shared.u64 t, %1; cvt.u32.u64 %0, t; }" : "=r"(a) : "l"(p));
    return a;
}
#define CPA16(s, g) asm volatile("cp.async.cg.shared.global [%0], [%1], 16;\n" :: "r"(s), "l"(g))
#define CPA_COMMIT() asm volatile("cp.async.commit_group;\n" ::: "memory")

#define LDMX4(r, a) \
    asm volatile("ldmatrix.sync.aligned.m8n8.x4.shared.b16 {%0,%1,%2,%3}, [%4];" \
        : "=r"((r)[0]), "=r"((r)[1]), "=r"((r)[2]), "=r"((r)[3]) : "r"(a))

#define MMA16816(d, a, b0_, b1_) \
    asm volatile("mma.sync.aligned.m16n8k16.row.col.f32.f16.f16.f32 " \
        "{%0,%1,%2,%3}, {%4,%5,%6,%7}, {%8,%9}, {%0,%1,%2,%3};" \
        : "+f"((d)[0]), "+f"((d)[1]), "+f"((d)[2]), "+f"((d)[3]) \
        : "r"((a)[0]), "r"((a)[1]), "r"((a)[2]), "r"((a)[3]), "r"(b0_), "r"(b1_))

// ---------------- prep kernels ----------------
__global__ void prep_props_kernel(const float* __restrict__ logits,
                                  const float* __restrict__ corners) {
    int i = blockIdx.x * blockDim.x + threadIdx.x;
    if (i >= BATCH*NPROP) return;
    const float* lg = logits + (size_t)i*NCLS;
    int am = 0; float best = lg[0];
    #pragma unroll
    for (int c = 1; c < NCLS; c++) { float v = lg[c]; if (v > best) { best = v; am = c; } }
    g_maskp[i] = (am != NCLS-1) ? 1.0f : 0.0f;
    const float* cr = corners + (size_t)i*24;
    float mn[3] = {cr[0], cr[1], cr[2]};
    float mx[3] = {cr[0], cr[1], cr[2]};
    #pragma unroll
    for (int k = 1; k < 8; k++)
        #pragma unroll
        for (int d = 0; d < 3; d++) {
            float v = cr[k*3+d];
            mn[d] = fminf(mn[d], v); mx[d] = fmaxf(mx[d], v);
        }
    float vol = 1.0f;
    #pragma unroll
    for (int d = 0; d < 3; d++) {
        g_mnp[i*3+d] = mn[d]; g_mxp[i*3+d] = mx[d];
        vol *= (mx[d] - mn[d]);
    }
    g_volp[i] = vol;
}

__global__ void prep_queries_kernel(const float* __restrict__ box_query) {
    int i = blockIdx.x * blockDim.x + threadIdx.x;
    if (i >= BATCH*NBQ) return;
    const float* cr = box_query + (size_t)i*24;
    float mn[3] = {cr[0], cr[1], cr[2]};
    float mx[3] = {cr[0], cr[1], cr[2]};
    #pragma unroll
    for (int k = 1; k < 8; k++)
        #pragma unroll
        for (int d = 0; d < 3; d++) {
            float v = cr[k*3+d];
            mn[d] = fminf(mn[d], v); mx[d] = fmaxf(mx[d], v);
        }
    float vol = 1.0f;
    #pragma unroll
    for (int d = 0; d < 3; d++) {
        g_mnq[i*3+d] = mn[d]; g_mxq[i*3+d] = mx[d];
        vol *= (mx[d] - mn[d]);
    }
    g_volq[i] = vol;
}

__global__ __launch_bounds__(256) void box_match_kernel(const float* __restrict__ prop_features) {
    int m = blockIdx.x;
    int b = m >> 6;
    int tid = threadIdx.x;
    float mnq0 = g_mnq[m*3+0], mnq1 = g_mnq[m*3+1], mnq2 = g_mnq[m*3+2];
    float mxq0 = g_mxq[m*3+0], mxq1 = g_mxq[m*3+1], mxq2 = g_mxq[m*3+2];
    float volq = g_volq[m];
    int pi = b*NPROP + tid;
    float i0 = fmaxf(fminf(mxq0, g_mxp[pi*3+0]) - fmaxf(mnq0, g_mnp[pi*3+0]), 0.0f);
    float i1 = fmaxf(fminf(mxq1, g_mxp[pi*3+1]) - fmaxf(mnq1, g_mnp[pi*3+1]), 0.0f);
    float i2 = fmaxf(fminf(mxq2, g_mxp[pi*3+2]) - fmaxf(mnq2, g_mnp[pi*3+2]), 0.0f);
    float inter = i0*i1*i2;
    float iou = inter / (volq + g_volp[pi] - inter + 1e-8f);
    iou *= g_maskp[pi];

    __shared__ float sv[256];
    __shared__ int   si[256];
    sv[tid] = iou; si[tid] = tid;
    __syncthreads();
    #pragma unroll
    for (int off = 128; off > 0; off >>= 1) {
        if (tid < off) {
            float v2 = sv[tid+off]; int j2 = si[tid+off];
            if (v2 > sv[tid] || (v2 == sv[tid] && j2 < si[tid])) { sv[tid] = v2; si[tid] = j2; }
        }
        __syncthreads();
    }
    int idx = si[0];
    float v = prop_features[((size_t)b*NPROP + idx)*CDIM + tid];
    g_Xbox[(size_t)m*K_BOX1 + tid] = __float2half(v);
}

__global__ __launch_bounds__(256) void click_prep_kernel(
    const float* __restrict__ click_query, const float* __restrict__ enc_xyz,
    const float* __restrict__ enc_features, const float* __restrict__ pc_min,
    const float* __restrict__ pc_max, const float* __restrict__ gauss_B) {
    int m = blockIdx.x;
    int b = m >> 6;
    int tid = threadIdx.x;
    float qx = click_query[m*3+0], qy = click_query[m*3+1], qz = click_query[m*3+2];

    const float* xyz = enc_xyz + (size_t)b*NPTS*3;
    // 4 independent min-trackers for MLP; indices ascend within each tracker.
    float bd[4] = {3.4e38f, 3.4e38f, 3.4e38f, 3.4e38f};
    int   bi[4] = {0, 0, 0, 0};
    #pragma unroll
    for (int j = 0; j < 16; j += 4) {
        #pragma unroll
        for (int u = 0; u < 4; u++) {
            int p = tid + 256*(j + u);
            float dx = qx - xyz[p*3+0];
            float dy = qy - xyz[p*3+1];
            float dz = qz - xyz[p*3+2];
            float d2 = dx*dx + dy*dy + dz*dz;
            if (d2 < bd[u]) { bd[u] = d2; bi[u] = p; }
        }
    }
    // merge trackers: global min-d2, smallest index on ties
    float bestd = bd[0]; int besti = bi[0];
    #pragma unroll
    for (int u = 1; u < 4; u++) {
        if (bd[u] < bestd || (bd[u] == bestd && bi[u] < besti)) { bestd = bd[u]; besti = bi[u]; }
    }
    __shared__ float sv[256];
    __shared__ int   si[256];
    sv[tid] = bestd; si[tid] = besti;
    __syncthreads();
    #pragma unroll
    for (int off = 128; off > 0; off >>= 1) {
        if (tid < off) {
            float v2 = sv[tid+off]; int j2 = si[tid+off];
            if (v2 < sv[tid] || (v2 == sv[tid] && j2 < si[tid])) { sv[tid] = v2; si[tid] = j2; }
        }
        __syncthreads();
    }
    int nn = si[0];
    size_t rb = (size_t)m*K_CLK1;
    g_Xclick[rb + tid] = __float2half(enc_features[((size_t)b*NPTS + nn)*CDIM + tid]);
    if (tid < 128) {
        float x0 = (qx - pc_min[b*3+0]) / (pc_max[b*3+0] - pc_min[b*3+0]);
        float y0 = (qy - pc_min[b*3+1]) / (pc_max[b*3+1] - pc_min[b*3+1]);
        float z0 = (qz - pc_min[b*3+2]) / (pc_max[b*3+2] - pc_min[b*3+2]);
        const float twopi = 6.283185307179586f;
        float proj = (x0*twopi)*gauss_B[tid] + (y0*twopi)*gauss_B[128+tid] + (z0*twopi)*gauss_B[256+tid];
        g_Xclick[rb + CDIM + tid]       = __float2half(sinf(proj));
        g_Xclick[rb + CDIM + 128 + tid] = __float2half(cosf(proj));
    }
}

// ---------------- fused weight conversion: all 4 weights in one launch ----------------
__global__ __launch_bounds__(256) void conv_all_kernel(
    const float* __restrict__ w0, __half* __restrict__ o0,   // box_w1  K=256  N=768
    const float* __restrict__ w1, __half* __restrict__ o1,   // click_w1 K=512 N=768
    const float* __restrict__ w2, __half* __restrict__ o2,   // box_w2  K=768  N=6144
    const float* __restrict__ w3, __half* __restrict__ o3)   // click_w2 K=768 N=6144
{
    const float* W; __half* B2; int K, N;
    switch (blockIdx.z) {
        case 0:  W = w0; B2 = o0; K = CDIM;   N = QHD;  break;
        case 1:  W = w1; B2 = o1; K = 2*CDIM; N = QHD;  break;
        case 2:  W = w2; B2 = o2; K = QHD;    N = NOUT; break;
        default: W = w3; B2 = o3; K = QHD;    N = NOUT; break;
    }
    int n0 = blockIdx.x * 32, k0 = blockIdx.y * 32;
    if (n0 >= N || k0 >= K) return;
    __shared__ float t[32][33];
    int tx = threadIdx.x, ty = threadIdx.y;   // block (32,8)
    #pragma unroll
    for (int j = 0; j < 4; j++) {
        int k = k0 + ty + j*8;
        t[ty + j*8][tx] = W[(size_t)k*N + n0 + tx];
    }
    __syncthreads();
    #pragma unroll
    for (int j = 0; j < 4; j++) {
        int n = n0 + ty + j*8;
        int k = k0 + tx;
        B2[(size_t)n*K + k] = __float2half(t[tx][ty + j*8]);
    }
}

// ---------------- HMMA fp16 GEMM ----------------
// D[M,N] = A[M,K] x B[N,K]^T; CTA tile 128x192, warp tile 64x48 (2x4 warps),
// BK=64, 4-stage cp.async pipeline, ONE barrier per chunk.
// mode 0: relu(d+bias) -> fp16 into outB [M,QHD]
// mode 1: d+bias -> outF + m*6144 + (m>>6)*BOX_HALF
// mode 2: same + BOX_HALF
#define BM 128
#define BN 192
#define NJ 6                   // 8-col frags per warp (48/8)
#define NT 3                   // 16-row ldmatrix groups per warp
#define A_STAGE 16384          // 128 x 64 fp16
#define B_STAGE 24576          // 192 x 64 fp16
#define STAGE_BYTES (A_STAGE + B_STAGE)   // 40960
#define NSTAGE 4
#define OFF_STAGE 1024
#define GEMM_SMEM (OFF_STAGE + NSTAGE*STAGE_BYTES)   // 164864

static __device__ __forceinline__ void load_chunk(
    const __half* A2, const __half* B2, int K,
    int bm, int bn, int c, uint32_t sbase, int stage)
{
    int t = threadIdx.x;
    uint32_t stA = sbase + OFF_STAGE + stage*STAGE_BYTES;
    uint32_t stB = stA + A_STAGE;
    // A: 128 rows x 128B = 1024 16B-units; 4 per thread
    #pragma unroll
    for (int i = 0; i < 4; i++) {
        int u = t + 256*i;
        int r = u >> 3, c16 = u & 7;
        uint32_t off = (uint32_t)r*128 + (uint32_t)((c16 ^ (r & 7)) << 4);
        CPA16(stA + off, (const char*)(A2 + (size_t)(bm + r)*K + c*64) + (c16 << 4));
    }
    // B: 192 rows x 128B = 1536 16B-units; 6 per thread
    #pragma unroll
    for (int i = 0; i < 6; i++) {
        int u = t + 256*i;
        int r = u >> 3, c16 = u & 7;
        uint32_t off = (uint32_t)r*128 + (uint32_t)((c16 ^ (r & 7)) << 4);
        CPA16(stB + off, (const char*)(B2 + (size_t)(bn + r)*K + c*64) + (c16 << 4));
    }
}

__global__ __launch_bounds__(256, 1) void gemm_hmma_kernel(
    const __half* A0, const __half* B0, const float* bias0,
    const __half* A1, const __half* B1, const float* bias1,
    int k0_, int k1_, int mode0_, int mode1_,
    float* outF, __half* outB0, __half* outB1)
{
    extern __shared__ char smem[];
    const int z = blockIdx.z;
    const __half* A2 = z ? A1 : A0;
    const __half* B2 = z ? B1 : B0;
    const float* bias = z ? bias1 : bias0;
    __half* outB = z ? outB1 : outB0;
    const int K = z ? k1_ : k0_;
    const int mode = z ? mode1_ : mode0_;
    const int bm = blockIdx.y * BM, bn = blockIdx.x * BN;
    const int tid = threadIdx.x, wid = tid >> 5, lane = tid & 31;
    const int warp_m = wid >> 2, warp_n = wid & 3;   // 2 x 4 warps, 64x48 each
    uint32_t sbase = smem_u32(smem);
    float* sBias = (float*)smem;
    if (tid < BN) sBias[tid] = bias[bn + tid];

    float acc[4][NJ][4];
    #pragma unroll
    for (int mi = 0; mi < 4; mi++)
        #pragma unroll
        for (int nj = 0; nj < NJ; nj++)
            #pragma unroll
            for (int e = 0; e < 4; e++) acc[mi][nj][e] = 0.0f;

    const int nch = K >> 6;
    load_chunk(A2, B2, K, bm, bn, 0, sbase, 0); CPA_COMMIT();
    load_chunk(A2, B2, K, bm, bn, 1, sbase, 1); CPA_COMMIT();
    load_chunk(A2, B2, K, bm, bn, 2, sbase, 2); CPA_COMMIT();

    const int lane15 = lane & 15, s7 = lane & 7, hic = lane >> 4;

    for (int c = 0; c < nch; c++) {
        // chunks issued so far: min(3+c, nch); need chunks <= c complete
        int rem = nch - 1 - c;
        if (rem >= 2)      { asm volatile("cp.async.wait_group 2;\n" ::: "memory"); }
        else if (rem == 1) { asm volatile("cp.async.wait_group 1;\n" ::: "memory"); }
        else               { asm volatile("cp.async.wait_group 0;\n" ::: "memory"); }
        __syncthreads();
        // issue next load BEFORE compute; stage (c+3)&3 was last read at chunk c-1,
        // and the barrier above proves all warps finished chunk c-1.
        if (c + 3 < nch) {
            load_chunk(A2, B2, K, bm, bn, c + 3, sbase, (c + 3) & 3);
            CPA_COMMIT();
        }

        int s = c & 3;
        uint32_t stA = sbase + OFF_STAGE + s*STAGE_BYTES;
        uint32_t stB = stA + A_STAGE;
        uint32_t aBase[4], bBase[NT];
        #pragma unroll
        for (int mi = 0; mi < 4; mi++)
            aBase[mi] = stA + (uint32_t)(warp_m*64 + mi*16 + lane15) * 128;
        #pragma unroll
        for (int nt = 0; nt < NT; nt++)
            bBase[nt] = stB + (uint32_t)(warp_n*48 + nt*16 + lane15) * 128;

        #pragma unroll
        for (int ks = 0; ks < 4; ks++) {
            uint32_t coff = (uint32_t)(((2*ks + hic) ^ s7) << 4);
            uint32_t afr[4][4], bfr[NT][4];
            #pragma unroll
            for (int mi = 0; mi < 4; mi++) LDMX4(afr[mi], aBase[mi] + coff);
            #pragma unroll
            for (int nt = 0; nt < NT; nt++) LDMX4(bfr[nt], bBase[nt] + coff);
            #pragma unroll
            for (int mi = 0; mi < 4; mi++)
                #pragma unroll
                for (int nj = 0; nj < NJ; nj++)
                    MMA16816(acc[mi][nj], afr[mi],
                             bfr[nj>>1][nj&1], bfr[nj>>1][2 + (nj&1)]);
        }
    }

    // ---- epilogue ----
    #pragma unroll
    for (int mi = 0; mi < 4; mi++) {
        int rr0 = warp_m*64 + mi*16 + (lane >> 2);
        #pragma unroll
        for (int h = 0; h < 2; h++) {
            int m = bm + rr0 + 8*h;
            size_t rowbase;
            if (mode == 0) rowbase = (size_t)m * K_G2;
            else {
                rowbase = (size_t)m * NOUT + (size_t)(m >> 6) * BOX_HALF;
                if (mode == 2) rowbase += BOX_HALF;
            }
            #pragma unroll
            for (int nj = 0; nj < NJ; nj++) {
                int cc = warp_n*48 + nj*8 + 2*(lane & 3);
                float v0 = acc[mi][nj][2*h+0] + sBias[cc];
                float v1 = acc[mi][nj][2*h+1] + sBias[cc+1];
                if (mode == 0) {
                    v0 = fmaxf(v0, 0.0f); v1 = fmaxf(v1, 0.0f);
                    __half2 hp; hp.x = __float2half(v0); hp.y = __float2half(v1);
                    *(__half2*)&outB[rowbase + (size_t)(bn + cc)] = hp;
                } else {
                    float2 v; v.x = v0; v.y = v1;
                    *(float2*)&outF[rowbase + bn + cc] = v;
                }
            }
        }
    }
}

// ---------------- mask tail ----------------
__global__ void mask_fill_kernel(const float* __restrict__ box_qmask,
                                 const float* __restrict__ click_qmask,
                                 float* __restrict__ out) {
    int i = blockIdx.x * blockDim.x + threadIdx.x;
    if (i >= BATCH * (NBQ+NCK) * VQ) return;
    int b = i / ((NBQ+NCK)*VQ);
    int s = i % ((NBQ+NCK)*VQ);
    float v;
    if (s < NBQ*VQ) v = box_qmask[b*NBQ + (s >> 3)];
    else            v = click_qmask[b*NCK + ((s - NBQ*VQ) >> 3)];
    out[FEAT_TOTAL + i] = v;
}

// ---------------- launch ----------------
extern "C" void kernel_launch(void* const* d_in, const int* in_sizes, int n_in,
                              void* d_out, int out_size) {
    const float* sem_cls_logits = (const float*)d_in[0];
    const float* prop_features  = (const float*)d_in[1];
    const float* box_corners    = (const float*)d_in[2];
    const float* enc_xyz        = (const float*)d_in[3];
    const float* enc_features   = (const float*)d_in[4];
    const float* pc_min         = (const float*)d_in[5];
    const float* pc_max         = (const float*)d_in[6];
    const float* box_query      = (const float*)d_in[7];
    const float* box_qmask      = (const float*)d_in[8];
    const float* click_query    = (const float*)d_in[9];
    const float* click_qmask    = (const float*)d_in[10];
    const float* gauss_B        = (const float*)d_in[11];
    const float* box_w1         = (const float*)d_in[12];
    const float* box_b1         = (const float*)d_in[13];
    const float* box_w2         = (const float*)d_in[14];
    const float* box_b2         = (const float*)d_in[15];
    const float* click_w1       = (const float*)d_in[16];
    const float* click_b1       = (const float*)d_in[17];
    const float* click_w2       = (const float*)d_in[18];
    const float* click_b2       = (const float*)d_in[19];
    float* out = (float*)d_out;

    __half *Xb, *Xc, *Hb, *Hc, *Wb1, *Wc1, *Wb2, *Wc2;
    cudaGetSymbolAddress((void**)&Xb,  g_Xbox);
    cudaGetSymbolAddress((void**)&Xc,  g_Xclick);
    cudaGetSymbolAddress((void**)&Hb,  g_Hbox);
    cudaGetSymbolAddress((void**)&Hc,  g_Hclick);
    cudaGetSymbolAddress((void**)&Wb1, g_Wb1);
    cudaGetSymbolAddress((void**)&Wc1, g_Wc1);
    cudaGetSymbolAddress((void**)&Wb2, g_Wb2);
    cudaGetSymbolAddress((void**)&Wc2, g_Wc2);

    cudaFuncSetAttribute(gemm_hmma_kernel,
                         cudaFuncAttributeMaxDynamicSharedMemorySize, GEMM_SMEM);

    // prep
    prep_props_kernel<<<(BATCH*NPROP + 255)/256, 256>>>(sem_cls_logits, box_corners);
    prep_queries_kernel<<<(BATCH*NBQ + 255)/256, 256>>>(box_query);
    box_match_kernel<<<MROWS, 256>>>(prop_features);
    click_prep_kernel<<<MROWS, 256>>>(click_query, enc_xyz, enc_features,
                                      pc_min, pc_max, gauss_B);
    // fused weight conversion (W[K,N] fp32 -> Wh[N,K] fp16), single launch
    {
        dim3 blk(32, 8);
        dim3 grid(NOUT/32, QHD/32, 4);   // max dims; ragged tiles early-exit
        conv_all_kernel<<<grid, blk>>>(box_w1, Wb1, click_w1, Wc1,
                                       box_w2, Wb2, click_w2, Wc2);
    }
    // GEMM1 (both branches): X @ W1 + b1, relu -> H (fp16)
    gemm_hmma_kernel<<<dim3(QHD/BN, MROWS/BM, 2), 256, GEMM_SMEM>>>(
        Xb, Wb1, box_b1, Xc, Wc1, click_b1,
        K_BOX1, K_CLK1, 0, 0, nullptr, Hb, Hc);
    // GEMM2 (both branches): H @ W2 + b2 -> out (interleaved layout)
    gemm_hmma_kernel<<<dim3(NOUT/BN, MROWS/BM, 2), 256, GEMM_SMEM>>>(
        Hb, Wb2, box_b2, Hc, Wc2, click_b2,
        K_G2, K_G2, 1, 2, out, nullptr, nullptr);

    mask_fill_kernel<<<(BATCH*(NBQ+NCK)*VQ + 255)/256, 256>>>(box_qmask, click_qmask, out);
}